// round 15
// baseline (speedup 1.0000x reference)
#include <cuda_runtime.h>
#include <cuda_fp16.h>

// Problem constants
#define B_  4
#define S_  512
#define D_  768
#define H_  12
#define DH_ 64
#define F_  2048
#define BS_ (B_ * S_)          // 2048
#define HK_ (H_ * S_)          // 6144
#define HD_ (H_ * DH_)         // 768  (flattened head dim)
#define NNZCAP 262144          // cap on padded mask nonzeros (expected ~226K)

// ---------------- scratch (device globals; no allocations allowed) ----------
__device__ __half g_Wa  [2 * F_ * D_];        // [0]=W_enc half, [1]=W_decT half
__device__ __half g_Wb  [2 * HD_ * D_];       // [0]=W_O flat,  [1]=W_V^T flat
__device__ float  g_EW  [2 * F_ * HD_];       // [0]=E1 [f][hdh], [1]=wd2 fp32
__device__ __half g_EWh [2 * F_ * HD_];       // [0]=E1 half, [1]=wd2 half
__device__ __half g_xlnH [B_ * S_ * D_];      // half x_ln
__device__ __half g_xvTH [B_ * HD_ * S_];     // [b][hdh][k] half (transposed xv)
__device__ __half g_zH   [B_ * S_ * HD_];     // [b][q][hdh] half (probs . xv)
__device__ __half g_probsH[B_ * H_ * S_ * S_];// half probs
__device__ __half g_uplnTh[F_ * BS_];         // [g][bk] half (gather source)
__device__ __half g_YtH  [B_ * F_ * HK_];     // [b][f][h*S+k] half (SPARSE ONLY)
__device__ __half g_vwvalH[16 * NNZCAP];      // [h(pad16)][j] half compact masked vw
__device__ int    g_gidx [NNZCAP];
__device__ int    g_cnt  [F_];                // REAL (unpadded) per-row counts
__device__ int    g_rowptr[F_ + 1];           // padded-to-16 CSR row ptr
__device__ float  g_t    [HD_];               // W_V^T . upb
__device__ float  g_c    [D_];
__device__ float  g_bias0[F_];
__device__ float  g_e    [F_];
__device__ int    g_maskmode;

// ---------------- mask dtype detector (parallel) -----------------------------
__global__ void detect_mask_k(const unsigned char* __restrict__ m) {
    __shared__ int sF, sB;
    int tid = threadIdx.x;
    if (tid == 0) { sF = 0; sB = 0; }
    __syncthreads();
    int f = 0, b = 0;
    for (int i = tid; i < 65536; i += 256) {
        unsigned char v = m[i];
        if (v == 63 || v == 128) f = 1;
        else if (v != 0 && (i & 3) != 0) b = 1;
    }
    if (f) atomicOr(&sF, 1);
    if (b) atomicOr(&sB, 1);
    __syncthreads();
    if (tid == 0) g_maskmode = sF ? 2 : (sB ? 0 : 1);
}

__device__ __forceinline__ int mask_nz(const unsigned char* m, long idx, int mode) {
    if (mode == 0) return m[idx] != 0;
    if (mode == 1) return ((const int*)m)[idx] != 0;
    return ((const float*)m)[idx] != 0.f;
}

// ---------------- mask CSR builders (rows padded to multiples of 16) ---------
__global__ void count_k(const unsigned char* __restrict__ m) {
    int w = (blockIdx.x * blockDim.x + threadIdx.x) >> 5;
    int lane = threadIdx.x & 31;
    if (w >= F_) return;
    int mode = g_maskmode;
    int cnt = 0;
    for (int g0 = 0; g0 < F_; g0 += 32) {
        int v = mask_nz(m, (long)w * F_ + g0 + lane, mode);
        cnt += __popc(__ballot_sync(0xffffffffu, v));
    }
    if (lane == 0) g_cnt[w] = cnt;
}

__global__ void scan_k() {
    __shared__ int part[256];
    int t = threadIdx.x;
    int base = t * 8;
    int s = 0;
    for (int i = 0; i < 8; i++) s += (g_cnt[base + i] + 15) & ~15;   // padded
    part[t] = s;
    __syncthreads();
    if (t == 0) {
        int r = 0;
        for (int i = 0; i < 256; i++) { int v = part[i]; part[i] = r; r += v; }
        g_rowptr[F_] = r;
    }
    __syncthreads();
    int r = part[t];
    for (int i = 0; i < 8; i++) {
        g_rowptr[base + i] = r;
        r += (g_cnt[base + i] + 15) & ~15;
    }
}

__global__ void fill_k(const unsigned char* __restrict__ m) {
    int w = (blockIdx.x * blockDim.x + threadIdx.x) >> 5;
    int lane = threadIdx.x & 31;
    if (w >= F_) return;
    int mode = g_maskmode;
    int base = g_rowptr[w];
    unsigned lt = (1u << lane) - 1u;
    for (int g0 = 0; g0 < F_; g0 += 32) {
        int g = g0 + lane;
        int v = mask_nz(m, (long)w * F_ + g, mode);
        unsigned bal = __ballot_sync(0xffffffffu, v);
        int pos = base + __popc(bal & lt);
        if (v && pos < NNZCAP) g_gidx[pos] = g;
        base += __popc(bal);
    }
    // pad slots -> g = 0 (vw pads are 0, so contribution is 0)
    int pe = g_rowptr[w + 1];
    if (pe > NNZCAP) pe = NNZCAP;
    for (int p = base + lane; p < pe; p += 32) g_gidx[p] = 0;
}

// ---------------- merged casts: W_enc, W_O, x_ln, probs -> half --------------
__global__ void casts_k(const float* __restrict__ wenc, const float* __restrict__ wo,
                        const float* __restrict__ probs,
                        const float* __restrict__ act, const float* __restrict__ lns) {
    long i = (long)blockIdx.x * blockDim.x + threadIdx.x;
    if (i < (long)F_ * D_)          g_Wa[i]     = __float2half(wenc[i]);
    if (i < (long)HD_ * D_)         g_Wb[i]     = __float2half(wo[i]);
    if (i < (long)B_ * S_ * D_)     g_xlnH[i]   = __float2half(act[i] / lns[i / D_]);
    if (i < (long)B_ * H_ * S_ * S_) g_probsH[i] = __float2half(probs[i]);
}

// W_V [h][m][dh] -> Wb[1] = WvTh[h*64+dh][m] half
__global__ void tpose_wv_k(const float* __restrict__ wv) {
    __shared__ float tile[32][33];
    int tx = threadIdx.x, ty = threadIdx.y;
    int h = blockIdx.z;
    int m0 = blockIdx.x * 32, dh0 = blockIdx.y * 32;
    #pragma unroll
    for (int i = 0; i < 32; i += 8)
        tile[ty + i][tx] = wv[((long)h * D_ + m0 + ty + i) * DH_ + dh0 + tx];
    __syncthreads();
    #pragma unroll
    for (int i = 0; i < 32; i += 8)
        g_Wb[(long)HD_ * D_ + ((long)h * DH_ + dh0 + ty + i) * D_ + m0 + tx] =
            __float2half(tile[tx][ty + i]);
}

// W_dec [m][g] -> Wa[1] = WdecT[g][m] half
__global__ void tpose_wdec_k(const float* __restrict__ wd) {
    __shared__ float tile[32][33];
    int tx = threadIdx.x, ty = threadIdx.y;
    int g = blockIdx.x * 32 + tx;
    int m0 = blockIdx.y * 32;
    #pragma unroll
    for (int i = 0; i < 32; i += 8)
        tile[ty + i][tx] = wd[(long)(m0 + ty + i) * F_ + g];
    __syncthreads();
    int mOut = m0 + tx;
    #pragma unroll
    for (int i = 0; i < 32; i += 8)
        g_Wa[(long)F_ * D_ + (long)(blockIdx.x * 32 + ty + i) * D_ + mOut] =
            __float2half(tile[tx][ty + i]);
}

__global__ void prep_upT_k(const float* __restrict__ pf, const float* __restrict__ lns) {
    __shared__ float tile[32][33];
    int tx = threadIdx.x, ty = threadIdx.y;
    int g = blockIdx.x * 32 + tx;
    int bk0 = blockIdx.y * 32;
    #pragma unroll
    for (int i = 0; i < 32; i += 8) {
        int bk = bk0 + ty + i;
        tile[ty + i][tx] = pf[(long)bk * F_ + g] / lns[bk];
    }
    __syncthreads();
    int bkOut = bk0 + tx;
    #pragma unroll
    for (int i = 0; i < 32; i += 8)
        g_uplnTh[(long)(blockIdx.x * 32 + ty + i) * BS_ + bkOut] =
            __float2half(tile[tx][ty + i]);
}

// ---------------- bias vectors (rank-64 path) --------------------------------
__global__ void t_k(const float* __restrict__ wv, const float* __restrict__ upb) {
    int h = blockIdx.x, dh = threadIdx.x;   // grid H_, block 64
    float s = 0.f;
    for (int m = 0; m < D_; m++)
        s += wv[((long)h * D_ + m) * DH_ + dh] * upb[m];
    g_t[h * DH_ + dh] = s;
}
__global__ void c2_k(const float* __restrict__ wo) {
    int d = blockIdx.x * 256 + threadIdx.x;  // grid 3, block 256
    if (d >= D_) return;
    float s = 0.f;
    for (int i = 0; i < HD_; i++) s += wo[(long)i * D_ + d] * g_t[i];
    g_c[d] = s;
}

__global__ void bias_vec_k(const float* __restrict__ W_enc,
                           const float* __restrict__ b_enc,
                           const float* __restrict__ b_dec) {
    int f = blockIdx.x * 256 + threadIdx.x;
    if (f >= F_) return;
    const float* row = W_enc + (long)f * D_;
    float s0 = 0.f, s1 = 0.f;
    for (int d = 0; d < D_; d++) {
        float w = row[d];
        s0 += w * b_dec[d];
        s1 += w * g_c[d];
    }
    g_bias0[f] = b_enc[f] - s0;
    g_e[f] = s1;
}

// ====== fp16 mma.sync m16n8k16 GEMM, cp.async 3-stage + ldmatrix (NT) ========
// OUTM 0: fp32 store.  1: half store.  2: fp32 + half.
#define MK   64
#define ROWH 72                               // halfs per smem row (64 + 8 pad)
#define NSTG 3
#define STGB (128 * ROWH * 2)                 // bytes per operand stage (18432)
#define MMA_SMEM (NSTG * 2 * STGB)            // 110592 bytes

__device__ __forceinline__ unsigned smem_u32(const void* p) {
    unsigned a;
    asm("{ .reg .u64 t; cvta.to.shared.u64 t, %1; cvt.u32.u64 %0, t; }" : "=r"(a) : "l"(p));
    return a;
}
__device__ __forceinline__ void cpasync16(unsigned dst, const void* src) {
    asm volatile("cp.async.cg.shared.global [%0], [%1], 16;" :: "r"(dst), "l"(src) : "memory");
}
__device__ __forceinline__ void ldsm_x4(unsigned addr, unsigned& r0, unsigned& r1,
                                        unsigned& r2, unsigned& r3) {
    asm volatile("ldmatrix.sync.aligned.m8n8.x4.shared.b16 {%0,%1,%2,%3}, [%4];"
                 : "=r"(r0), "=r"(r1), "=r"(r2), "=r"(r3) : "r"(addr));
}
__device__ __forceinline__ void ldsm_x2(unsigned addr, unsigned& r0, unsigned& r1) {
    asm volatile("ldmatrix.sync.aligned.m8n8.x2.shared.b16 {%0,%1}, [%2];"
                 : "=r"(r0), "=r"(r1) : "r"(addr));
}
__device__ __forceinline__ void ldsm_x4t(unsigned addr, unsigned& r0, unsigned& r1,
                                         unsigned& r2, unsigned& r3) {
    asm volatile("ldmatrix.sync.aligned.m8n8.x4.trans.shared.b16 {%0,%1,%2,%3}, [%4];"
                 : "=r"(r0), "=r"(r1), "=r"(r2), "=r"(r3) : "r"(addr));
}
__device__ __forceinline__ void mma16816(float* c, unsigned a0, unsigned a1,
                                         unsigned a2, unsigned a3,
                                         unsigned b0, unsigned b1) {
    asm volatile(
        "mma.sync.aligned.m16n8k16.row.col.f32.f16.f16.f32 "
        "{%0,%1,%2,%3}, {%4,%5,%6,%7}, {%8,%9}, {%0,%1,%2,%3};"
        : "+f"(c[0]), "+f"(c[1]), "+f"(c[2]), "+f"(c[3])
        : "r"(a0), "r"(a1), "r"(a2), "r"(a3), "r"(b0), "r"(b1));
}

template<int OUTM>
__global__ __launch_bounds__(256, 2)
void mma_k(const __half* __restrict__ Ag, const __half* __restrict__ Bg,
           float* __restrict__ Cg, __half* __restrict__ Chg,
           int K, int lda, int ldb, int ldc, int Hdim,
           long sAb, long sAh, long sBb, long sBh, long sCb, long sCh) {
    extern __shared__ __align__(16) char smc[];

    const int zb = blockIdx.z / Hdim, zh = blockIdx.z % Hdim;
    const __half* A = Ag + zb * sAb + zh * sAh;
    const __half* B = Bg + zb * sBb + zh * sBh;
    float*  C  = Cg  + zb * sCb + zh * sCh;
    __half* Ch = Chg + zb * sCb + zh * sCh;

    const int row0 = blockIdx.y * 128, col0 = blockIdx.x * 128;
    const int tid = threadIdx.x, wid = tid >> 5, lane = tid & 31;
    const int warpM = (wid & 1) * 64, warpN = (wid >> 1) * 32;
    const int lr = lane >> 2, lc = lane & 3;

    float acc[4][4][4];
    #pragma unroll
    for (int im = 0; im < 4; im++)
        #pragma unroll
        for (int in = 0; in < 4; in++)
            #pragma unroll
            for (int q = 0; q < 4; q++) acc[im][in][q] = 0.f;

    const int nch = K / MK;

    const unsigned sb32 = smem_u32(smc);
    const int lrow8 = lane & 7, sel = lane >> 3;
    const unsigned aoff = (unsigned)(((warpM + (sel & 1) * 8 + lrow8) * ROWH
                                      + (sel >> 1) * 8)) * 2u;
    const unsigned boff = (unsigned)(((warpN + lrow8) * ROWH
                                      + ((lane >> 3) & 1) * 8)) * 2u;

    auto issue = [&](int c) {
        unsigned sa = sb32 + (unsigned)((c % NSTG) * 2 * STGB);
        const int k0 = c * MK;
        #pragma unroll
        for (int i = 0; i < 4; i++) {
            int u = i * 256 + tid;
            int r = u >> 3, q = u & 7;
            unsigned off = (unsigned)(r * ROWH + q * 8) * 2u;
            cpasync16(sa + off, A + (long)(row0 + r) * lda + k0 + q * 8);
            cpasync16(sa + (unsigned)STGB + off, B + (long)(col0 + r) * ldb + k0 + q * 8);
        }
    };

    issue(0);
    asm volatile("cp.async.commit_group;" ::: "memory");
    if (nch > 1) issue(1);
    asm volatile("cp.async.commit_group;" ::: "memory");

    for (int c = 0; c < nch; c++) {
        asm volatile("cp.async.wait_group 1;" ::: "memory");
        __syncthreads();
        if (c + 2 < nch) issue(c + 2);
        asm volatile("cp.async.commit_group;" ::: "memory");

        const unsigned sAa = sb32 + (unsigned)((c % NSTG) * 2 * STGB);
        const unsigned sBa = sAa + (unsigned)STGB;
        #pragma unroll
        for (int ks = 0; ks < 4; ks++) {
            unsigned af[4][4], bf[4][2];
            #pragma unroll
            for (int im = 0; im < 4; im++)
                ldsm_x4(sAa + aoff + (unsigned)((im * 16 * ROWH + ks * 16) * 2),
                        af[im][0], af[im][1], af[im][2], af[im][3]);
            #pragma unroll
            for (int in = 0; in < 4; in++)
                ldsm_x2(sBa + boff + (unsigned)((in * 8 * ROWH + ks * 16) * 2),
                        bf[in][0], bf[in][1]);
            #pragma unroll
            for (int im = 0; im < 4; im++)
                #pragma unroll
                for (int in = 0; in < 4; in++)
                    mma16816(acc[im][in], af[im][0], af[im][1], af[im][2], af[im][3],
                             bf[in][0], bf[in][1]);
        }
    }

    #pragma unroll
    for (int im = 0; im < 4; im++) {
        int r = row0 + warpM + im * 16 + lr;
        #pragma unroll
        for (int in = 0; in < 4; in++) {
            int cc = col0 + warpN + in * 8 + lc * 2;
            float v0 = acc[im][in][0], v1 = acc[im][in][1];
            float v2 = acc[im][in][2], v3 = acc[im][in][3];
            if (OUTM == 0 || OUTM == 2) {
                *reinterpret_cast<float2*>(C + (long)r * ldc + cc) = make_float2(v0, v1);
                *reinterpret_cast<float2*>(C + (long)(r + 8) * ldc + cc) = make_float2(v2, v3);
            }
            if (OUTM == 1 || OUTM == 2) {
                *reinterpret_cast<__half2*>(Ch + (long)r * ldc + cc) =
                    __floats2half2_rn(v0, v1);
                *reinterpret_cast<__half2*>(Ch + (long)(r + 8) * ldc + cc) =
                    __floats2half2_rn(v2, v3);
            }
        }
    }
}

// ======== z_k: Z[b][q][h*64+n] = probs[b,h] (512x512) . xvT[h*64+n][k] =======
#define ZROW 72
#define ZSTG ((128 + 64) * ZROW * 2)           // 27648 B per stage
#define Z_SMEM (3 * ZSTG)                      // 82944 B

__global__ __launch_bounds__(256, 2)
void z_k() {
    extern __shared__ __align__(16) char smz[];
    const int b = blockIdx.z / H_, h = blockIdx.z % H_;
    const __half* A = g_probsH + (long)(b * H_ + h) * (S_ * S_);  // [q][k]
    const __half* Bx = g_xvTH + (long)b * HD_ * S_ + (long)(h * DH_) * S_; // [n][k]
    const int row0 = blockIdx.y * 128;
    const int tid = threadIdx.x, wid = tid >> 5, lane = tid & 31;
    const int warpM = (wid & 3) * 32, warpN = (wid >> 2) * 32;
    const int lr = lane >> 2, lc = lane & 3;

    float acc[2][4][4];
    #pragma unroll
    for (int im = 0; im < 2; im++)
        #pragma unroll
        for (int in = 0; in < 4; in++)
            #pragma unroll
            for (int q = 0; q < 4; q++) acc[im][in][q] = 0.f;

    const int nch = min(8, 2 * (int)blockIdx.y + 2);
    const unsigned sb32 = smem_u32(smz);
    const int lrow8 = lane & 7, sel = lane >> 3;
    const unsigned aoff = (unsigned)(((warpM + (sel & 1) * 8 + lrow8) * ZROW
                                      + (sel >> 1) * 8)) * 2u;
    const unsigned boff = (unsigned)(((warpN + lrow8) * ZROW
                                      + ((lane >> 3) & 1) * 8)) * 2u;

    auto issue = [&](int c) {
        unsigned sa = sb32 + (unsigned)((c % 3) * ZSTG);
        const int k0 = c * 64;
        #pragma unroll
        for (int i = 0; i < 4; i++) {
            int u = i * 256 + tid;
            int r = u >> 3, q = u & 7;
            cpasync16(sa + (unsigned)(r * ZROW + q * 8) * 2u,
                      A + (long)(row0 + r) * S_ + k0 + q * 8);
        }
        #pragma unroll
        for (int i = 0; i < 2; i++) {
            int u = i * 256 + tid;
            int r = u >> 3, q = u & 7;
            cpasync16(sa + (unsigned)(128 * ZROW) * 2u + (unsigned)(r * ZROW + q * 8) * 2u,
                      Bx + (long)r * S_ + k0 + q * 8);
        }
    };

    issue(0);
    asm volatile("cp.async.commit_group;" ::: "memory");
    if (nch > 1) issue(1);
    asm volatile("cp.async.commit_group;" ::: "memory");

    for (int c = 0; c < nch; c++) {
        asm volatile("cp.async.wait_group 1;" ::: "memory");
        __syncthreads();
        if (c + 2 < nch) issue(c + 2);
        asm volatile("cp.async.commit_group;" ::: "memory");

        const unsigned sAa = sb32 + (unsigned)((c % 3) * ZSTG);
        const unsigned sBa = sAa + (unsigned)(128 * ZROW) * 2u;
        #pragma unroll
        for (int ks = 0; ks < 4; ks++) {
            unsigned af[2][4], bf[4][2];
            #pragma unroll
            for (int im = 0; im < 2; im++)
                ldsm_x4(sAa + aoff + (unsigned)((im * 16 * ZROW + ks * 16) * 2),
                        af[im][0], af[im][1], af[im][2], af[im][3]);
            #pragma unroll
            for (int in = 0; in < 4; in++)
                ldsm_x2(sBa + boff + (unsigned)((in * 8 * ZROW + ks * 16) * 2),
                        bf[in][0], bf[in][1]);
            #pragma unroll
            for (int im = 0; im < 2; im++)
                #pragma unroll
                for (int in = 0; in < 4; in++)
                    mma16816(acc[im][in], af[im][0], af[im][1], af[im][2], af[im][3],
                             bf[in][0], bf[in][1]);
        }
    }

    __half* Z = g_zH + (long)b * S_ * HD_;
    #pragma unroll
    for (int im = 0; im < 2; im++) {
        int r = row0 + warpM + im * 16 + lr;
        #pragma unroll
        for (int in = 0; in < 4; in++) {
            int cc = h * DH_ + warpN + in * 8 + lc * 2;
            *reinterpret_cast<__half2*>(Z + (long)r * HD_ + cc) =
                __floats2half2_rn(acc[im][in][0], acc[im][in][1]);
            *reinterpret_cast<__half2*>(Z + (long)(r + 8) * HD_ + cc) =
                __floats2half2_rn(acc[im][in][2], acc[im][in][3]);
        }
    }
}

// ======== out_k: FUSED final GEMM ===========================================
// out[b][q][f] = Z[b][q,:HD] . E1h[f,:HD]^T                (chunks 0..11)
//             + sum_h probs[b,h][q,:] . Yt[b][f, hS:hS+S]  (causal chunks)
//             + bias0[f] + e[f]/lns[b,q]
#define DENSE_CH (HD_ / MK)                   // 12 dense chunks (K = 768)

__global__ __launch_bounds__(256, 2)
void out_k(float* __restrict__ out, const float* __restrict__ Lg) {
    extern __shared__ __align__(16) char smc[];
    const int zb = blockIdx.z;
    const __half* Z = g_zH + (long)zb * S_ * HD_;
    const __half* P = g_probsH + (long)zb * H_ * (S_ * S_);
    const __half* Y = g_YtH + (long)zb * F_ * HK_;
    float* C = out + (long)zb * S_ * F_;

    const int row0 = blockIdx.y * 128, col0 = blockIdx.x * 128;
    const int tid = threadIdx.x, wid = tid >> 5, lane = tid & 31;
    const int warpM = (wid & 1) * 64, warpN = (wid >> 1) * 32;
    const int lr = lane >> 2, lc = lane & 3;

    float acc[4][4][4];
    #pragma unroll
    for (int im = 0; im < 4; im++)
        #pragma unroll
        for (int in = 0; in < 4; in++)
            #pragma unroll
            for (int q = 0; q < 4; q++) acc[im][in][q] = 0.f;

    const int nchh = min(8, 2 * (int)blockIdx.y + 2);
    const int nch = DENSE_CH + H_ * nchh;    // 12 dense + causal sparse chunks

    const unsigned sb32 = smem_u32(smc);
    const int lrow8 = lane & 7, sel = lane >> 3;
    const unsigned aoff = (unsigned)(((warpM + (sel & 1) * 8 + lrow8) * ROWH
                                      + (sel >> 1) * 8)) * 2u;
    const unsigned boff = (unsigned)(((warpN + lrow8) * ROWH
                                      + ((lane >> 3) & 1) * 8)) * 2u;

    auto issue = [&](int c) {
        unsigned sa = sb32 + (unsigned)((c % NSTG) * 2 * STGB);
        const __half *Ab, *Bb;
        int kA, kB, ldaL, ldbL;
        if (c < DENSE_CH) {
            kA = c * MK; kB = kA;
            Ab = Z; ldaL = HD_;
            Bb = g_EWh; ldbL = HD_;
        } else {
            int idx = c - DENSE_CH;
            int hh = idx / nchh, cc = idx - hh * nchh;
            kA = cc * MK;
            kB = hh * S_ + kA;
            Ab = P + (long)hh * (S_ * S_); ldaL = S_;
            Bb = Y; ldbL = HK_;
        }
        #pragma unroll
        for (int i = 0; i < 4; i++) {
            int u = i * 256 + tid;
            int r = u >> 3, q = u & 7;
            unsigned off = (unsigned)(r * ROWH + q * 8) * 2u;
            cpasync16(sa + off, Ab + (long)(row0 + r) * ldaL + kA + q * 8);
            cpasync16(sa + (unsigned)STGB + off, Bb + (long)(col0 + r) * ldbL + kB + q * 8);
        }
    };

    issue(0);
    asm volatile("cp.async.commit_group;" ::: "memory");
    issue(1);
    asm volatile("cp.async.commit_group;" ::: "memory");

    for (int c = 0; c < nch; c++) {
        asm volatile("cp.async.wait_group 1;" ::: "memory");
        __syncthreads();
        if (c + 2 < nch) issue(c + 2);
        asm volatile("cp.async.commit_group;" ::: "memory");

        const unsigned sAa = sb32 + (unsigned)((c % NSTG) * 2 * STGB);
        const unsigned sBa = sAa + (unsigned)STGB;
        #pragma unroll
        for (int ks = 0; ks < 4; ks++) {
            unsigned af[4][4], bf[4][2];
            #pragma unroll
            for (int im = 0; im < 4; im++)
                ldsm_x4(sAa + aoff + (unsigned)((im * 16 * ROWH + ks * 16) * 2),
                        af[im][0], af[im][1], af[im][2], af[im][3]);
            #pragma unroll
            for (int in = 0; in < 4; in++)
                ldsm_x2(sBa + boff + (unsigned)((in * 8 * ROWH + ks * 16) * 2),
                        bf[in][0], bf[in][1]);
            #pragma unroll
            for (int im = 0; im < 4; im++)
                #pragma unroll
                for (int in = 0; in < 4; in++)
                    mma16816(acc[im][in], af[im][0], af[im][1], af[im][2], af[im][3],
                             bf[in][0], bf[in][1]);
        }
    }

    #pragma unroll
    for (int im = 0; im < 4; im++) {
        int r = row0 + warpM + im * 16 + lr;
        float il0 = 1.f / Lg[zb * S_ + r];
        float il1 = 1.f / Lg[zb * S_ + r + 8];
        #pragma unroll
        for (int in = 0; in < 4; in++) {
            int cc = col0 + warpN + in * 8 + lc * 2;
            float b0 = g_bias0[cc], b1 = g_bias0[cc + 1];
            float e0 = g_e[cc],     e1 = g_e[cc + 1];
            *reinterpret_cast<float2*>(C + (long)r * F_ + cc) =
                make_float2(acc[im][in][0] + b0 + e0 * il0,
                            acc[im][in][1] + b1 + e1 * il0);
            *reinterpret_cast<float2*>(C + (long)(r + 8) * F_ + cc) =
                make_float2(acc[im][in][2] + b0 + e0 * il1,
                            acc[im][in][3] + b1 + e1 * il1);
        }
    }
}

// ---------- sparse vw: vwvalH[h][j] = sum_dh E1[f][h64+dh]*wd2h[g][h64+dh] ---
__global__ __launch_bounds__(256)
void vw_sparse_k() {
    __shared__ float sE[HD_];
    const int f = blockIdx.x;
    const int tid = threadIdx.x;

    for (int i = tid; i < HD_; i += 256) sE[i] = g_EW[(long)f * HD_ + i];
    __syncthreads();

    const int jb = g_rowptr[f];
    int jePad = g_rowptr[f + 1];
    if (jePad > NNZCAP) jePad = NNZCAP;
    const int jeReal = min(jb + g_cnt[f], jePad);

    const int jl = tid / H_, h = tid - jl * H_;   // 21 j-slots x 12 heads = 252
    if (tid < 252) {
        for (int j = jb + jl; j < jePad; j += 21) {
            float s = 0.f;
            if (j < jeReal) {
                const int g = g_gidx[j];
                const __half* w = g_EWh + (long)F_ * HD_ + (long)g * HD_ + h * DH_;
                const float* e = sE + h * DH_;
                #pragma unroll
                for (int d = 0; d < DH_; d += 8) {
                    uint4 wp = *reinterpret_cast<const uint4*>(w + d);
                    const __half2* wh = reinterpret_cast<const __half2*>(&wp);
                    #pragma unroll
                    for (int q = 0; q < 4; q++) {
                        float2 wv = __half22float2(wh[q]);
                        s += e[d + q * 2 + 0] * wv.x;
                        s += e[d + q * 2 + 1] * wv.y;
                    }
                }
            }
            g_vwvalH[(long)h * NNZCAP + j] = __float2half(s);
        }
    }
    {
        int jl2 = tid >> 2, hr = 12 + (tid & 3);
        for (int j = jb + jl2; j < jePad; j += 64)
            g_vwvalH[(long)hr * NNZCAP + j] = __half(0.f);
    }
}

// ======== spMM as gather-GEMM (tensor cores), PURE WRITE into YtH ============
#define NBK  512                               // bk columns per block
#define UPADW2 (NBK + 8)                       // halfs per gathered row
#define SPMM_STG (16 * UPADW2 * 2)             // 16640 B per stage
#define SPMM_SMEM (2 * SPMM_STG)               // 33280 B

__global__ __launch_bounds__(256, 4)
void spmm_mma_k() {
    extern __shared__ __align__(16) char sms[];
    const int f = blockIdx.x;
    const int bkbase = blockIdx.y * NBK;
    const int jb = g_rowptr[f];
    int je = g_rowptr[f + 1];
    if (je > NNZCAP) je = jb + ((NNZCAP - jb) & ~15);
    const int nch = (je - jb) >> 4;

    const int tid = threadIdx.x, wid = tid >> 5, lane = tid & 31;
    const int bk0 = wid * 64;
    const unsigned sb32 = smem_u32(sms);

    float acc[8][4];
    #pragma unroll
    for (int nt = 0; nt < 8; nt++)
        #pragma unroll
        for (int q = 0; q < 4; q++) acc[nt][q] = 0.f;

    auto gather = [&](int c) {
        unsigned sa = sb32 + (unsigned)((c & 1) * SPMM_STG);
        const int j0 = jb + c * 16;
        #pragma unroll
        for (int i = 0; i < 4; i++) {
            int u = i * 256 + tid;             // 0..1023
            int row = u >> 6, q = u & 63;      // row 0..15, 16B-quad 0..63
            int g = g_gidx[j0 + row];
            cpasync16(sa + (unsigned)(row * UPADW2 + q * 8) * 2u,
                      g_uplnTh + (long)g * BS_ + bkbase + q * 8);
        }
    };

    if (nch > 0) {
        gather(0);
        asm volatile("cp.async.commit_group;" ::: "memory");

        const int arow = lane >> 2, acol = (lane & 3) * 2;
        const unsigned ldoff = (unsigned)((lane & 15) * UPADW2 + (lane >> 4) * 8) * 2u;

        for (int c = 0; c < nch; c++) {
            if (c + 1 < nch) gather(c + 1);
            asm volatile("cp.async.commit_group;" ::: "memory");
            asm volatile("cp.async.wait_group 1;" ::: "memory");
            __syncthreads();

            const int j0 = jb + c * 16;
            unsigned a0 = *reinterpret_cast<const unsigned*>(
                g_vwvalH + (long)arow * NNZCAP + j0 + acol);
            unsigned a1 = *reinterpret_cast<const unsigned*>(
                g_vwvalH + (long)(arow + 8) * NNZCAP + j0 + acol);
            unsigned a2 = *reinterpret_cast<const unsigned*>(
                g_vwvalH + (long)arow * NNZCAP + j0 + 8 + acol);
            unsigned a3 = *reinterpret_cast<const unsigned*>(
                g_vwvalH + (long)(arow + 8) * NNZCAP + j0 + 8 + acol);

            const unsigned sa = sb32 + (unsigned)((c & 1) * SPMM_STG) + ldoff;
            #pragma unroll
            for (int nt = 0; nt < 8; nt += 2) {
                unsigned b0, b1, b2, b3;
                ldsm_x4t(sa + (unsigned)(bk0 + nt * 8) * 2u, b0, b1, b2, b3);
                mma16816(acc[nt],     a0, a1, a2, a3, b0, b1);
                mma16816(acc[nt + 1], a0, a1, a2, a3, b2, b3);
            }
            __syncthreads();
        }
    }

    // epilogue: PURE STORE into YtH (sparse-only tensor; zero rows covered)
    const int h0 = lane >> 2, h1 = h0 + 8;
    #pragma unroll
    for (int nt = 0; nt < 8; nt++) {
        int col = bkbase + bk0 + nt * 8 + (lane & 3) * 2;
        int b = col >> 9, k = col & (S_ - 1);
        long base = ((long)b * F_ + f) * HK_ + k;
        *reinterpret_cast<__half2*>(&g_YtH[base + h0 * S_]) =
            __floats2half2_rn(acc[nt][0], acc[nt][1]);
        if (h1 < H_)
            *reinterpret_cast<__half2*>(&g_YtH[base + h1 * S_]) =
                __floats2half2_rn(acc[nt][2], acc[nt][3]);
    }
}

// ---------------------------------------------------------------------------
extern "C" void kernel_launch(void* const* d_in, const int* in_sizes, int n_in,
                              void* d_out, int out_size) {
    (void)in_sizes; (void)n_in; (void)out_size;
    const float* act   = (const float*)d_in[0];
    const float* lns   = (const float*)d_in[1];
    const float* probs = (const float*)d_in[2];
    const float* pf    = (const float*)d_in[3];
    const float* W_O   = (const float*)d_in[4];
    const float* W_V   = (const float*)d_in[5];
    const float* W_enc = (const float*)d_in[6];
    const float* b_enc = (const float*)d_in[7];
    const float* b_dec = (const float*)d_in[8];
    const float* W_dec = (const float*)d_in[9];
    const float* upb   = (const float*)d_in[10];
    const unsigned char* mask = (const unsigned char*)d_in[11];
    float* out = (float*)d_out;

    float *EW;
    __half *Wa, *Wb, *EWh, *xlnH, *xvTH;
    cudaGetSymbolAddress((void**)&Wa,   g_Wa);
    cudaGetSymbolAddress((void**)&Wb,   g_Wb);
    cudaGetSymbolAddress((void**)&EW,   g_EW);
    cudaGetSymbolAddress((void**)&EWh,  g_EWh);
    cudaGetSymbolAddress((void**)&xlnH, g_xlnH);
    cudaGetSymbolAddress((void**)&xvTH, g_xvTH);

    const long SD  = (long)S_ * D_;
    const long FD  = (long)F_ * D_;
    const long HDD = (long)HD_ * D_;
    const long FHD = (long)F_ * HD_;

    cudaFuncSetAttribute(mma_k<2>, cudaFuncAttributeMaxDynamicSharedMemorySize, MMA_SMEM);
    cudaFuncSetAttribute(mma_k<1>, cudaFuncAttributeMaxDynamicSharedMemorySize, MMA_SMEM);
    cudaFuncSetAttribute(out_k, cudaFuncAttributeMaxDynamicSharedMemorySize, MMA_SMEM);
    cudaFuncSetAttribute(z_k, cudaFuncAttributeMaxDynamicSharedMemorySize, Z_SMEM);
    cudaFuncSetAttribute(spmm_mma_k, cudaFuncAttributeMaxDynamicSharedMemorySize, SPMM_SMEM);

    detect_mask_k<<<1, 256>>>(mask);
    count_k<<<(F_ * 32 + 255) / 256, 256>>>(mask);
    scan_k<<<1, 256>>>();
    fill_k<<<(F_ * 32 + 255) / 256, 256>>>(mask);

    casts_k<<<(int)(((long)B_ * H_ * S_ * S_ + 255) / 256), 256>>>(
        W_enc, W_O, probs, act, lns);
    tpose_wv_k<<<dim3(D_ / 32, DH_ / 32, H_), dim3(32, 8)>>>(W_V);
    tpose_wdec_k<<<dim3(F_ / 32, D_ / 32), dim3(32, 8)>>>(W_dec);
    prep_upT_k<<<dim3(F_ / 32, BS_ / 32), dim3(32, 8)>>>(pf, lns);

    // bias vectors (rank-64)
    t_k<<<H_, DH_>>>(W_V, upb);
    c2_k<<<3, 256>>>(W_O);
    bias_vec_k<<<F_ / 256, 256>>>(W_enc, b_enc, b_dec);

    // E1 and wd2 in one batched GEMM (z=0: E1, z=1: wd2; fp32 + half outputs)
    mma_k<2><<<dim3(HD_ / 128, F_ / 128, 2), 256, MMA_SMEM>>>(
        Wa, Wb, EW, EWh, D_, D_, D_, HD_, 2,
        0, FD, 0, HDD, 0, FHD);

    // xvT[b][hdh][k] = WvT[hdh,:] . xlnH[b][k,:]   (half out)
    mma_k<1><<<dim3(S_ / 128, HD_ / 128, B_), 256, MMA_SMEM>>>(
        Wb + HDD, xlnH, out /*dummy*/, xvTH, D_, D_, D_, S_, 1,
        0, 0, SD, 0, (long)HD_ * S_, 0);

    // sparse vw (fp32 acc, wd2 in half, padded)
    vw_sparse_k<<<F_, 256>>>();

    // spMM on tensor cores: gather-GEMM, PURE WRITE of sparse Yt (occ 4)
    spmm_mma_k<<<dim3(F_, BS_ / NBK), 256, SPMM_SMEM>>>();

    // Z[b][q][hdh] = probs[b,h] . xvT (causal)
    z_k<<<dim3(1, S_ / 128, B_ * H_), 256, Z_SMEM>>>();

    // FUSED: out = Z.E1^T + probs.Yt_sparse(causal) + bias  (sole writer)
    out_k<<<dim3(F_ / 128, S_ / 128, B_), 256, MMA_SMEM>>>(out, lns);
}

// round 16
// speedup vs baseline: 1.0475x; 1.0475x over previous
#include <cuda_runtime.h>
#include <cuda_fp16.h>

// Problem constants
#define B_  4
#define S_  512
#define D_  768
#define H_  12
#define DH_ 64
#define F_  2048
#define BS_ (B_ * S_)          // 2048
#define HK_ (H_ * S_)          // 6144
#define HD_ (H_ * DH_)         // 768  (flattened head dim)
#define NNZCAP 262144          // cap on padded mask nonzeros (expected ~226K)

// ---------------- scratch (device globals; no allocations allowed) ----------
__device__ __half g_Wa  [2 * F_ * D_];        // [0]=W_enc half, [1]=W_decT half
__device__ __half g_Wb  [2 * HD_ * D_];       // [0]=W_O flat,  [1]=W_V^T flat
__device__ float  g_EW  [2 * F_ * HD_];       // [0]=E1 [f][hdh], [1]=wd2 fp32
__device__ __half g_EWh [2 * F_ * HD_];       // [0]=E1 half, [1]=wd2 half
__device__ __half g_xlnH [B_ * S_ * D_];      // half x_ln
__device__ __half g_xvTH [B_ * HD_ * S_];     // [b][hdh][k] half (transposed xv)
__device__ __half g_zH   [B_ * S_ * HD_];     // [b][q][hdh] half (probs . xv)
__device__ __half g_probsH[B_ * H_ * S_ * S_];// half probs
__device__ __half g_uplnTh[F_ * BS_];         // [g][bk] half (gather source)
__device__ __half g_YtH  [B_ * F_ * HK_];     // [b][f][h*S+k] half (SPARSE ONLY)
__device__ __half g_vwvalH[16 * NNZCAP];      // [h(pad16)][j] half compact masked vw
__device__ int    g_gidx [NNZCAP];
__device__ int    g_cnt  [F_];                // REAL (unpadded) per-row counts
__device__ int    g_rowptr[F_ + 1];           // padded-to-16 CSR row ptr
__device__ float  g_t    [HD_];               // W_V^T . upb
__device__ float  g_c    [D_];
__device__ float  g_bias0[F_];
__device__ float  g_e    [F_];
__device__ int    g_maskmode;

// ---------------- mask dtype detector (parallel) -----------------------------
__global__ void detect_mask_k(const unsigned char* __restrict__ m) {
    __shared__ int sF, sB;
    int tid = threadIdx.x;
    if (tid == 0) { sF = 0; sB = 0; }
    __syncthreads();
    int f = 0, b = 0;
    for (int i = tid; i < 65536; i += 256) {
        unsigned char v = m[i];
        if (v == 63 || v == 128) f = 1;
        else if (v != 0 && (i & 3) != 0) b = 1;
    }
    if (f) atomicOr(&sF, 1);
    if (b) atomicOr(&sB, 1);
    __syncthreads();
    if (tid == 0) g_maskmode = sF ? 2 : (sB ? 0 : 1);
}

__device__ __forceinline__ int mask_nz(const unsigned char* m, long idx, int mode) {
    if (mode == 0) return m[idx] != 0;
    if (mode == 1) return ((const int*)m)[idx] != 0;
    return ((const float*)m)[idx] != 0.f;
}

// ---------------- mask CSR builders (rows padded to multiples of 16) ---------
__global__ void count_k(const unsigned char* __restrict__ m) {
    int w = (blockIdx.x * blockDim.x + threadIdx.x) >> 5;
    int lane = threadIdx.x & 31;
    if (w >= F_) return;
    int mode = g_maskmode;
    int cnt = 0;
    for (int g0 = 0; g0 < F_; g0 += 32) {
        int v = mask_nz(m, (long)w * F_ + g0 + lane, mode);
        cnt += __popc(__ballot_sync(0xffffffffu, v));
    }
    if (lane == 0) g_cnt[w] = cnt;
}

__global__ void scan_k() {
    __shared__ int part[256];
    int t = threadIdx.x;
    int base = t * 8;
    int s = 0;
    for (int i = 0; i < 8; i++) s += (g_cnt[base + i] + 15) & ~15;   // padded
    part[t] = s;
    __syncthreads();
    if (t == 0) {
        int r = 0;
        for (int i = 0; i < 256; i++) { int v = part[i]; part[i] = r; r += v; }
        g_rowptr[F_] = r;
    }
    __syncthreads();
    int r = part[t];
    for (int i = 0; i < 8; i++) {
        g_rowptr[base + i] = r;
        r += (g_cnt[base + i] + 15) & ~15;
    }
}

__global__ void fill_k(const unsigned char* __restrict__ m) {
    int w = (blockIdx.x * blockDim.x + threadIdx.x) >> 5;
    int lane = threadIdx.x & 31;
    if (w >= F_) return;
    int mode = g_maskmode;
    int base = g_rowptr[w];
    unsigned lt = (1u << lane) - 1u;
    for (int g0 = 0; g0 < F_; g0 += 32) {
        int g = g0 + lane;
        int v = mask_nz(m, (long)w * F_ + g, mode);
        unsigned bal = __ballot_sync(0xffffffffu, v);
        int pos = base + __popc(bal & lt);
        if (v && pos < NNZCAP) g_gidx[pos] = g;
        base += __popc(bal);
    }
    // pad slots -> g = 0 (vw pads are 0, so contribution is 0)
    int pe = g_rowptr[w + 1];
    if (pe > NNZCAP) pe = NNZCAP;
    for (int p = base + lane; p < pe; p += 32) g_gidx[p] = 0;
}

// ---------------- merged casts: W_enc, W_O, x_ln, probs -> half --------------
__global__ void casts_k(const float* __restrict__ wenc, const float* __restrict__ wo,
                        const float* __restrict__ probs,
                        const float* __restrict__ act, const float* __restrict__ lns) {
    long i = (long)blockIdx.x * blockDim.x + threadIdx.x;
    if (i < (long)F_ * D_)          g_Wa[i]     = __float2half(wenc[i]);
    if (i < (long)HD_ * D_)         g_Wb[i]     = __float2half(wo[i]);
    if (i < (long)B_ * S_ * D_)     g_xlnH[i]   = __float2half(act[i] / lns[i / D_]);
    if (i < (long)B_ * H_ * S_ * S_) g_probsH[i] = __float2half(probs[i]);
}

// W_V [h][m][dh] -> Wb[1] = WvTh[h*64+dh][m] half
__global__ void tpose_wv_k(const float* __restrict__ wv) {
    __shared__ float tile[32][33];
    int tx = threadIdx.x, ty = threadIdx.y;
    int h = blockIdx.z;
    int m0 = blockIdx.x * 32, dh0 = blockIdx.y * 32;
    #pragma unroll
    for (int i = 0; i < 32; i += 8)
        tile[ty + i][tx] = wv[((long)h * D_ + m0 + ty + i) * DH_ + dh0 + tx];
    __syncthreads();
    #pragma unroll
    for (int i = 0; i < 32; i += 8)
        g_Wb[(long)HD_ * D_ + ((long)h * DH_ + dh0 + ty + i) * D_ + m0 + tx] =
            __float2half(tile[tx][ty + i]);
}

// W_dec [m][g] -> Wa[1] = WdecT[g][m] half
__global__ void tpose_wdec_k(const float* __restrict__ wd) {
    __shared__ float tile[32][33];
    int tx = threadIdx.x, ty = threadIdx.y;
    int g = blockIdx.x * 32 + tx;
    int m0 = blockIdx.y * 32;
    #pragma unroll
    for (int i = 0; i < 32; i += 8)
        tile[ty + i][tx] = wd[(long)(m0 + ty + i) * F_ + g];
    __syncthreads();
    int mOut = m0 + tx;
    #pragma unroll
    for (int i = 0; i < 32; i += 8)
        g_Wa[(long)F_ * D_ + (long)(blockIdx.x * 32 + ty + i) * D_ + mOut] =
            __float2half(tile[tx][ty + i]);
}

__global__ void prep_upT_k(const float* __restrict__ pf, const float* __restrict__ lns) {
    __shared__ float tile[32][33];
    int tx = threadIdx.x, ty = threadIdx.y;
    int g = blockIdx.x * 32 + tx;
    int bk0 = blockIdx.y * 32;
    #pragma unroll
    for (int i = 0; i < 32; i += 8) {
        int bk = bk0 + ty + i;
        tile[ty + i][tx] = pf[(long)bk * F_ + g] / lns[bk];
    }
    __syncthreads();
    int bkOut = bk0 + tx;
    #pragma unroll
    for (int i = 0; i < 32; i += 8)
        g_uplnTh[(long)(blockIdx.x * 32 + ty + i) * BS_ + bkOut] =
            __float2half(tile[tx][ty + i]);
}

// ---------------- bias vectors (rank-64 path) --------------------------------
__global__ void t_k(const float* __restrict__ wv, const float* __restrict__ upb) {
    int h = blockIdx.x, dh = threadIdx.x;   // grid H_, block 64
    float s = 0.f;
    for (int m = 0; m < D_; m++)
        s += wv[((long)h * D_ + m) * DH_ + dh] * upb[m];
    g_t[h * DH_ + dh] = s;
}
__global__ void c2_k(const float* __restrict__ wo) {
    int d = blockIdx.x * 256 + threadIdx.x;  // grid 3, block 256
    if (d >= D_) return;
    float s = 0.f;
    for (int i = 0; i < HD_; i++) s += wo[(long)i * D_ + d] * g_t[i];
    g_c[d] = s;
}

__global__ void bias_vec_k(const float* __restrict__ W_enc,
                           const float* __restrict__ b_enc,
                           const float* __restrict__ b_dec) {
    int f = blockIdx.x * 256 + threadIdx.x;
    if (f >= F_) return;
    const float* row = W_enc + (long)f * D_;
    float s0 = 0.f, s1 = 0.f;
    for (int d = 0; d < D_; d++) {
        float w = row[d];
        s0 += w * b_dec[d];
        s1 += w * g_c[d];
    }
    g_bias0[f] = b_enc[f] - s0;
    g_e[f] = s1;
}

// ====== fp16 mma.sync m16n8k16 GEMM, cp.async 3-stage + ldmatrix (NT) ========
// OUTM 0: fp32 store.  1: half store.  2: fp32 + half.
#define MK   64
#define ROWH 72                               // halfs per smem row (64 + 8 pad)
#define NSTG 3
#define STGB (128 * ROWH * 2)                 // bytes per operand stage (18432)
#define MMA_SMEM (NSTG * 2 * STGB)            // 110592 bytes

__device__ __forceinline__ unsigned smem_u32(const void* p) {
    unsigned a;
    asm("{ .reg .u64 t; cvta.to.shared.u64 t, %1; cvt.u32.u64 %0, t; }" : "=r"(a) : "l"(p));
    return a;
}
__device__ __forceinline__ void cpasync16(unsigned dst, const void* src) {
    asm volatile("cp.async.cg.shared.global [%0], [%1], 16;" :: "r"(dst), "l"(src) : "memory");
}
__device__ __forceinline__ void ldsm_x4(unsigned addr, unsigned& r0, unsigned& r1,
                                        unsigned& r2, unsigned& r3) {
    asm volatile("ldmatrix.sync.aligned.m8n8.x4.shared.b16 {%0,%1,%2,%3}, [%4];"
                 : "=r"(r0), "=r"(r1), "=r"(r2), "=r"(r3) : "r"(addr));
}
__device__ __forceinline__ void ldsm_x2(unsigned addr, unsigned& r0, unsigned& r1) {
    asm volatile("ldmatrix.sync.aligned.m8n8.x2.shared.b16 {%0,%1}, [%2];"
                 : "=r"(r0), "=r"(r1) : "r"(addr));
}
__device__ __forceinline__ void ldsm_x4t(unsigned addr, unsigned& r0, unsigned& r1,
                                         unsigned& r2, unsigned& r3) {
    asm volatile("ldmatrix.sync.aligned.m8n8.x4.trans.shared.b16 {%0,%1,%2,%3}, [%4];"
                 : "=r"(r0), "=r"(r1), "=r"(r2), "=r"(r3) : "r"(addr));
}
__device__ __forceinline__ void mma16816(float* c, unsigned a0, unsigned a1,
                                         unsigned a2, unsigned a3,
                                         unsigned b0, unsigned b1) {
    asm volatile(
        "mma.sync.aligned.m16n8k16.row.col.f32.f16.f16.f32 "
        "{%0,%1,%2,%3}, {%4,%5,%6,%7}, {%8,%9}, {%0,%1,%2,%3};"
        : "+f"(c[0]), "+f"(c[1]), "+f"(c[2]), "+f"(c[3])
        : "r"(a0), "r"(a1), "r"(a2), "r"(a3), "r"(b0), "r"(b1));
}

template<int OUTM>
__global__ __launch_bounds__(256, 2)
void mma_k(const __half* __restrict__ Ag, const __half* __restrict__ Bg,
           float* __restrict__ Cg, __half* __restrict__ Chg,
           int K, int lda, int ldb, int ldc, int Hdim,
           long sAb, long sAh, long sBb, long sBh, long sCb, long sCh) {
    extern __shared__ __align__(16) char smc[];

    const int zb = blockIdx.z / Hdim, zh = blockIdx.z % Hdim;
    const __half* A = Ag + zb * sAb + zh * sAh;
    const __half* B = Bg + zb * sBb + zh * sBh;
    float*  C  = Cg  + zb * sCb + zh * sCh;
    __half* Ch = Chg + zb * sCb + zh * sCh;

    const int row0 = blockIdx.y * 128, col0 = blockIdx.x * 128;
    const int tid = threadIdx.x, wid = tid >> 5, lane = tid & 31;
    const int warpM = (wid & 1) * 64, warpN = (wid >> 1) * 32;
    const int lr = lane >> 2, lc = lane & 3;

    float acc[4][4][4];
    #pragma unroll
    for (int im = 0; im < 4; im++)
        #pragma unroll
        for (int in = 0; in < 4; in++)
            #pragma unroll
            for (int q = 0; q < 4; q++) acc[im][in][q] = 0.f;

    const int nch = K / MK;

    const unsigned sb32 = smem_u32(smc);
    const int lrow8 = lane & 7, sel = lane >> 3;
    const unsigned aoff = (unsigned)(((warpM + (sel & 1) * 8 + lrow8) * ROWH
                                      + (sel >> 1) * 8)) * 2u;
    const unsigned boff = (unsigned)(((warpN + lrow8) * ROWH
                                      + ((lane >> 3) & 1) * 8)) * 2u;

    auto issue = [&](int c) {
        unsigned sa = sb32 + (unsigned)((c % NSTG) * 2 * STGB);
        const int k0 = c * MK;
        #pragma unroll
        for (int i = 0; i < 4; i++) {
            int u = i * 256 + tid;
            int r = u >> 3, q = u & 7;
            unsigned off = (unsigned)(r * ROWH + q * 8) * 2u;
            cpasync16(sa + off, A + (long)(row0 + r) * lda + k0 + q * 8);
            cpasync16(sa + (unsigned)STGB + off, B + (long)(col0 + r) * ldb + k0 + q * 8);
        }
    };

    issue(0);
    asm volatile("cp.async.commit_group;" ::: "memory");
    if (nch > 1) issue(1);
    asm volatile("cp.async.commit_group;" ::: "memory");

    for (int c = 0; c < nch; c++) {
        asm volatile("cp.async.wait_group 1;" ::: "memory");
        __syncthreads();
        if (c + 2 < nch) issue(c + 2);
        asm volatile("cp.async.commit_group;" ::: "memory");

        const unsigned sAa = sb32 + (unsigned)((c % NSTG) * 2 * STGB);
        const unsigned sBa = sAa + (unsigned)STGB;
        #pragma unroll
        for (int ks = 0; ks < 4; ks++) {
            unsigned af[4][4], bf[4][2];
            #pragma unroll
            for (int im = 0; im < 4; im++)
                ldsm_x4(sAa + aoff + (unsigned)((im * 16 * ROWH + ks * 16) * 2),
                        af[im][0], af[im][1], af[im][2], af[im][3]);
            #pragma unroll
            for (int in = 0; in < 4; in++)
                ldsm_x2(sBa + boff + (unsigned)((in * 8 * ROWH + ks * 16) * 2),
                        bf[in][0], bf[in][1]);
            #pragma unroll
            for (int im = 0; im < 4; im++)
                #pragma unroll
                for (int in = 0; in < 4; in++)
                    mma16816(acc[im][in], af[im][0], af[im][1], af[im][2], af[im][3],
                             bf[in][0], bf[in][1]);
        }
    }

    #pragma unroll
    for (int im = 0; im < 4; im++) {
        int r = row0 + warpM + im * 16 + lr;
        #pragma unroll
        for (int in = 0; in < 4; in++) {
            int cc = col0 + warpN + in * 8 + lc * 2;
            float v0 = acc[im][in][0], v1 = acc[im][in][1];
            float v2 = acc[im][in][2], v3 = acc[im][in][3];
            if (OUTM == 0 || OUTM == 2) {
                *reinterpret_cast<float2*>(C + (long)r * ldc + cc) = make_float2(v0, v1);
                *reinterpret_cast<float2*>(C + (long)(r + 8) * ldc + cc) = make_float2(v2, v3);
            }
            if (OUTM == 1 || OUTM == 2) {
                *reinterpret_cast<__half2*>(Ch + (long)r * ldc + cc) =
                    __floats2half2_rn(v0, v1);
                *reinterpret_cast<__half2*>(Ch + (long)(r + 8) * ldc + cc) =
                    __floats2half2_rn(v2, v3);
            }
        }
    }
}

// ======== z_k: Z[b][q][h*64+n] = probs[b,h] (512x512) . xvT[h*64+n][k] =======
#define ZROW 72
#define ZSTG ((128 + 64) * ZROW * 2)           // 27648 B per stage
#define Z_SMEM (3 * ZSTG)                      // 82944 B

__global__ __launch_bounds__(256, 2)
void z_k() {
    extern __shared__ __align__(16) char smz[];
    const int b = blockIdx.z / H_, h = blockIdx.z % H_;
    const __half* A = g_probsH + (long)(b * H_ + h) * (S_ * S_);  // [q][k]
    const __half* Bx = g_xvTH + (long)b * HD_ * S_ + (long)(h * DH_) * S_; // [n][k]
    const int row0 = blockIdx.y * 128;
    const int tid = threadIdx.x, wid = tid >> 5, lane = tid & 31;
    const int warpM = (wid & 3) * 32, warpN = (wid >> 2) * 32;
    const int lr = lane >> 2, lc = lane & 3;

    float acc[2][4][4];
    #pragma unroll
    for (int im = 0; im < 2; im++)
        #pragma unroll
        for (int in = 0; in < 4; in++)
            #pragma unroll
            for (int q = 0; q < 4; q++) acc[im][in][q] = 0.f;

    const int nch = min(8, 2 * (int)blockIdx.y + 2);
    const unsigned sb32 = smem_u32(smz);
    const int lrow8 = lane & 7, sel = lane >> 3;
    const unsigned aoff = (unsigned)(((warpM + (sel & 1) * 8 + lrow8) * ZROW
                                      + (sel >> 1) * 8)) * 2u;
    const unsigned boff = (unsigned)(((warpN + lrow8) * ZROW
                                      + ((lane >> 3) & 1) * 8)) * 2u;

    auto issue = [&](int c) {
        unsigned sa = sb32 + (unsigned)((c % 3) * ZSTG);
        const int k0 = c * 64;
        #pragma unroll
        for (int i = 0; i < 4; i++) {
            int u = i * 256 + tid;
            int r = u >> 3, q = u & 7;
            cpasync16(sa + (unsigned)(r * ZROW + q * 8) * 2u,
                      A + (long)(row0 + r) * S_ + k0 + q * 8);
        }
        #pragma unroll
        for (int i = 0; i < 2; i++) {
            int u = i * 256 + tid;
            int r = u >> 3, q = u & 7;
            cpasync16(sa + (unsigned)(128 * ZROW) * 2u + (unsigned)(r * ZROW + q * 8) * 2u,
                      Bx + (long)r * S_ + k0 + q * 8);
        }
    };

    issue(0);
    asm volatile("cp.async.commit_group;" ::: "memory");
    if (nch > 1) issue(1);
    asm volatile("cp.async.commit_group;" ::: "memory");

    for (int c = 0; c < nch; c++) {
        asm volatile("cp.async.wait_group 1;" ::: "memory");
        __syncthreads();
        if (c + 2 < nch) issue(c + 2);
        asm volatile("cp.async.commit_group;" ::: "memory");

        const unsigned sAa = sb32 + (unsigned)((c % 3) * ZSTG);
        const unsigned sBa = sAa + (unsigned)(128 * ZROW) * 2u;
        #pragma unroll
        for (int ks = 0; ks < 4; ks++) {
            unsigned af[2][4], bf[4][2];
            #pragma unroll
            for (int im = 0; im < 2; im++)
                ldsm_x4(sAa + aoff + (unsigned)((im * 16 * ZROW + ks * 16) * 2),
                        af[im][0], af[im][1], af[im][2], af[im][3]);
            #pragma unroll
            for (int in = 0; in < 4; in++)
                ldsm_x2(sBa + boff + (unsigned)((in * 8 * ZROW + ks * 16) * 2),
                        bf[in][0], bf[in][1]);
            #pragma unroll
            for (int im = 0; im < 2; im++)
                #pragma unroll
                for (int in = 0; in < 4; in++)
                    mma16816(acc[im][in], af[im][0], af[im][1], af[im][2], af[im][3],
                             bf[in][0], bf[in][1]);
        }
    }

    __half* Z = g_zH + (long)b * S_ * HD_;
    #pragma unroll
    for (int im = 0; im < 2; im++) {
        int r = row0 + warpM + im * 16 + lr;
        #pragma unroll
        for (int in = 0; in < 4; in++) {
            int cc = h * DH_ + warpN + in * 8 + lc * 2;
            *reinterpret_cast<__half2*>(Z + (long)r * HD_ + cc) =
                __floats2half2_rn(acc[im][in][0], acc[im][in][1]);
            *reinterpret_cast<__half2*>(Z + (long)(r + 8) * HD_ + cc) =
                __floats2half2_rn(acc[im][in][2], acc[im][in][3]);
        }
    }
}

// ======== out_k: FUSED final GEMM ===========================================
// out[b][q][f] = Z[b][q,:HD] . E1h[f,:HD]^T                (chunks 0..11)
//             + sum_h probs[b,h][q,:] . Yt[b][f, hS:hS+S]  (causal chunks)
//             + bias0[f] + e[f]/lns[b,q]
#define DENSE_CH (HD_ / MK)                   // 12 dense chunks (K = 768)

__global__ __launch_bounds__(256, 2)
void out_k(float* __restrict__ out, const float* __restrict__ Lg) {
    extern __shared__ __align__(16) char smc[];
    const int zb = blockIdx.z;
    const __half* Z = g_zH + (long)zb * S_ * HD_;
    const __half* P = g_probsH + (long)zb * H_ * (S_ * S_);
    const __half* Y = g_YtH + (long)zb * F_ * HK_;
    float* C = out + (long)zb * S_ * F_;

    const int row0 = blockIdx.y * 128, col0 = blockIdx.x * 128;
    const int tid = threadIdx.x, wid = tid >> 5, lane = tid & 31;
    const int warpM = (wid & 1) * 64, warpN = (wid >> 1) * 32;
    const int lr = lane >> 2, lc = lane & 3;

    float acc[4][4][4];
    #pragma unroll
    for (int im = 0; im < 4; im++)
        #pragma unroll
        for (int in = 0; in < 4; in++)
            #pragma unroll
            for (int q = 0; q < 4; q++) acc[im][in][q] = 0.f;

    const int nchh = min(8, 2 * (int)blockIdx.y + 2);
    const int nch = DENSE_CH + H_ * nchh;    // 12 dense + causal sparse chunks

    const unsigned sb32 = smem_u32(smc);
    const int lrow8 = lane & 7, sel = lane >> 3;
    const unsigned aoff = (unsigned)(((warpM + (sel & 1) * 8 + lrow8) * ROWH
                                      + (sel >> 1) * 8)) * 2u;
    const unsigned boff = (unsigned)(((warpN + lrow8) * ROWH
                                      + ((lane >> 3) & 1) * 8)) * 2u;

    auto issue = [&](int c) {
        unsigned sa = sb32 + (unsigned)((c % NSTG) * 2 * STGB);
        const __half *Ab, *Bb;
        int kA, kB, ldaL, ldbL;
        if (c < DENSE_CH) {
            kA = c * MK; kB = kA;
            Ab = Z; ldaL = HD_;
            Bb = g_EWh; ldbL = HD_;
        } else {
            int idx = c - DENSE_CH;
            int hh = idx / nchh, cc = idx - hh * nchh;
            kA = cc * MK;
            kB = hh * S_ + kA;
            Ab = P + (long)hh * (S_ * S_); ldaL = S_;
            Bb = Y; ldbL = HK_;
        }
        #pragma unroll
        for (int i = 0; i < 4; i++) {
            int u = i * 256 + tid;
            int r = u >> 3, q = u & 7;
            unsigned off = (unsigned)(r * ROWH + q * 8) * 2u;
            cpasync16(sa + off, Ab + (long)(row0 + r) * ldaL + kA + q * 8);
            cpasync16(sa + (unsigned)STGB + off, Bb + (long)(col0 + r) * ldbL + kB + q * 8);
        }
    };

    issue(0);
    asm volatile("cp.async.commit_group;" ::: "memory");
    issue(1);
    asm volatile("cp.async.commit_group;" ::: "memory");

    for (int c = 0; c < nch; c++) {
        asm volatile("cp.async.wait_group 1;" ::: "memory");
        __syncthreads();
        if (c + 2 < nch) issue(c + 2);
        asm volatile("cp.async.commit_group;" ::: "memory");

        const unsigned sAa = sb32 + (unsigned)((c % NSTG) * 2 * STGB);
        const unsigned sBa = sAa + (unsigned)STGB;
        #pragma unroll
        for (int ks = 0; ks < 4; ks++) {
            unsigned af[4][4], bf[4][2];
            #pragma unroll
            for (int im = 0; im < 4; im++)
                ldsm_x4(sAa + aoff + (unsigned)((im * 16 * ROWH + ks * 16) * 2),
                        af[im][0], af[im][1], af[im][2], af[im][3]);
            #pragma unroll
            for (int in = 0; in < 4; in++)
                ldsm_x2(sBa + boff + (unsigned)((in * 8 * ROWH + ks * 16) * 2),
                        bf[in][0], bf[in][1]);
            #pragma unroll
            for (int im = 0; im < 4; im++)
                #pragma unroll
                for (int in = 0; in < 4; in++)
                    mma16816(acc[im][in], af[im][0], af[im][1], af[im][2], af[im][3],
                             bf[in][0], bf[in][1]);
        }
    }

    #pragma unroll
    for (int im = 0; im < 4; im++) {
        int r = row0 + warpM + im * 16 + lr;
        float il0 = 1.f / Lg[zb * S_ + r];
        float il1 = 1.f / Lg[zb * S_ + r + 8];
        #pragma unroll
        for (int in = 0; in < 4; in++) {
            int cc = col0 + warpN + in * 8 + lc * 2;
            float b0 = g_bias0[cc], b1 = g_bias0[cc + 1];
            float e0 = g_e[cc],     e1 = g_e[cc + 1];
            *reinterpret_cast<float2*>(C + (long)r * F_ + cc) =
                make_float2(acc[im][in][0] + b0 + e0 * il0,
                            acc[im][in][1] + b1 + e1 * il0);
            *reinterpret_cast<float2*>(C + (long)(r + 8) * F_ + cc) =
                make_float2(acc[im][in][2] + b0 + e0 * il1,
                            acc[im][in][3] + b1 + e1 * il1);
        }
    }
}

// ---------- sparse vw: vwvalH[h][j] = sum_dh E1[f][h64+dh]*wd2h[g][h64+dh] ---
__global__ __launch_bounds__(256)
void vw_sparse_k() {
    __shared__ float sE[HD_];
    const int f = blockIdx.x;
    const int tid = threadIdx.x;

    for (int i = tid; i < HD_; i += 256) sE[i] = g_EW[(long)f * HD_ + i];
    __syncthreads();

    const int jb = g_rowptr[f];
    int jePad = g_rowptr[f + 1];
    if (jePad > NNZCAP) jePad = NNZCAP;
    const int jeReal = min(jb + g_cnt[f], jePad);

    const int jl = tid / H_, h = tid - jl * H_;   // 21 j-slots x 12 heads = 252
    if (tid < 252) {
        for (int j = jb + jl; j < jePad; j += 21) {
            float s = 0.f;
            if (j < jeReal) {
                const int g = g_gidx[j];
                const __half* w = g_EWh + (long)F_ * HD_ + (long)g * HD_ + h * DH_;
                const float* e = sE + h * DH_;
                #pragma unroll
                for (int d = 0; d < DH_; d += 8) {
                    uint4 wp = *reinterpret_cast<const uint4*>(w + d);
                    const __half2* wh = reinterpret_cast<const __half2*>(&wp);
                    #pragma unroll
                    for (int q = 0; q < 4; q++) {
                        float2 wv = __half22float2(wh[q]);
                        s += e[d + q * 2 + 0] * wv.x;
                        s += e[d + q * 2 + 1] * wv.y;
                    }
                }
            }
            g_vwvalH[(long)h * NNZCAP + j] = __float2half(s);
        }
    }
    {
        int jl2 = tid >> 2, hr = 12 + (tid & 3);
        for (int j = jb + jl2; j < jePad; j += 64)
            g_vwvalH[(long)hr * NNZCAP + j] = __half(0.f);
    }
}

// ======== spMM as gather-GEMM (tensor cores), PURE WRITE into YtH ============
// Per (f, half-of-bk): Yt[h][bk] += sum_j vwvalH[h][j] * uplnTh[gidx[j]][bk]
// M=16 (h pad), K=nnz_f (padded 16), N=1024 per block. grid (F_, 2), 8 warps,
// warp w owns 128 bk cols. Double-buffered cp.async row gather, occupancy 3.
#define NBK  1024                              // bk columns per block
#define UPADW2 (NBK + 8)                       // halfs per gathered row
#define SPMM_STG (16 * UPADW2 * 2)             // 33024 B per stage
#define SPMM_SMEM (2 * SPMM_STG)               // 66048 B

__global__ __launch_bounds__(256, 3)
void spmm_mma_k() {
    extern __shared__ __align__(16) char sms[];
    const int f = blockIdx.x;
    const int bkbase = blockIdx.y * NBK;
    const int jb = g_rowptr[f];
    int je = g_rowptr[f + 1];
    if (je > NNZCAP) je = jb + ((NNZCAP - jb) & ~15);
    const int nch = (je - jb) >> 4;

    const int tid = threadIdx.x, wid = tid >> 5, lane = tid & 31;
    const int bk0 = wid * 128;                 // within block's 1024
    const unsigned sb32 = smem_u32(sms);

    float acc[16][4];
    #pragma unroll
    for (int nt = 0; nt < 16; nt++)
        #pragma unroll
        for (int q = 0; q < 4; q++) acc[nt][q] = 0.f;

    auto gather = [&](int c) {
        unsigned sa = sb32 + (unsigned)((c & 1) * SPMM_STG);
        const int j0 = jb + c * 16;
        #pragma unroll
        for (int i = 0; i < 8; i++) {
            int u = i * 256 + tid;             // 0..2047
            int row = u >> 7, q = u & 127;     // row 0..15, 16B-quad 0..127
            int g = g_gidx[j0 + row];
            cpasync16(sa + (unsigned)(row * UPADW2 + q * 8) * 2u,
                      g_uplnTh + (long)g * BS_ + bkbase + q * 8);
        }
    };

    if (nch > 0) {
        gather(0);
        asm volatile("cp.async.commit_group;" ::: "memory");

        const int arow = lane >> 2, acol = (lane & 3) * 2;
        const unsigned ldoff = (unsigned)((lane & 15) * UPADW2 + (lane >> 4) * 8) * 2u;

        for (int c = 0; c < nch; c++) {
            if (c + 1 < nch) gather(c + 1);
            asm volatile("cp.async.commit_group;" ::: "memory");
            asm volatile("cp.async.wait_group 1;" ::: "memory");
            __syncthreads();

            const int j0 = jb + c * 16;
            unsigned a0 = *reinterpret_cast<const unsigned*>(
                g_vwvalH + (long)arow * NNZCAP + j0 + acol);
            unsigned a1 = *reinterpret_cast<const unsigned*>(
                g_vwvalH + (long)(arow + 8) * NNZCAP + j0 + acol);
            unsigned a2 = *reinterpret_cast<const unsigned*>(
                g_vwvalH + (long)arow * NNZCAP + j0 + 8 + acol);
            unsigned a3 = *reinterpret_cast<const unsigned*>(
                g_vwvalH + (long)(arow + 8) * NNZCAP + j0 + 8 + acol);

            const unsigned sa = sb32 + (unsigned)((c & 1) * SPMM_STG) + ldoff;
            #pragma unroll
            for (int nt = 0; nt < 16; nt += 2) {
                unsigned b0, b1, b2, b3;
                ldsm_x4t(sa + (unsigned)(bk0 + nt * 8) * 2u, b0, b1, b2, b3);
                mma16816(acc[nt],     a0, a1, a2, a3, b0, b1);
                mma16816(acc[nt + 1], a0, a1, a2, a3, b2, b3);
            }
            __syncthreads();
        }
    }

    // epilogue: PURE STORE into YtH (sparse-only tensor; zero rows covered)
    const int h0 = lane >> 2, h1 = h0 + 8;
    #pragma unroll
    for (int nt = 0; nt < 16; nt++) {
        int col = bkbase + bk0 + nt * 8 + (lane & 3) * 2;
        int b = col >> 9, k = col & (S_ - 1);
        long base = ((long)b * F_ + f) * HK_ + k;
        *reinterpret_cast<__half2*>(&g_YtH[base + h0 * S_]) =
            __floats2half2_rn(acc[nt][0], acc[nt][1]);
        if (h1 < H_)
            *reinterpret_cast<__half2*>(&g_YtH[base + h1 * S_]) =
                __floats2half2_rn(acc[nt][2], acc[nt][3]);
    }
}

// ---------------------------------------------------------------------------
extern "C" void kernel_launch(void* const* d_in, const int* in_sizes, int n_in,
                              void* d_out, int out_size) {
    (void)in_sizes; (void)n_in; (void)out_size;
    const float* act   = (const float*)d_in[0];
    const float* lns   = (const float*)d_in[1];
    const float* probs = (const float*)d_in[2];
    const float* pf    = (const float*)d_in[3];
    const float* W_O   = (const float*)d_in[4];
    const float* W_V   = (const float*)d_in[5];
    const float* W_enc = (const float*)d_in[6];
    const float* b_enc = (const float*)d_in[7];
    const float* b_dec = (const float*)d_in[8];
    const float* W_dec = (const float*)d_in[9];
    const float* upb   = (const float*)d_in[10];
    const unsigned char* mask = (const unsigned char*)d_in[11];
    float* out = (float*)d_out;

    float *EW;
    __half *Wa, *Wb, *EWh, *xlnH, *xvTH;
    cudaGetSymbolAddress((void**)&Wa,   g_Wa);
    cudaGetSymbolAddress((void**)&Wb,   g_Wb);
    cudaGetSymbolAddress((void**)&EW,   g_EW);
    cudaGetSymbolAddress((void**)&EWh,  g_EWh);
    cudaGetSymbolAddress((void**)&xlnH, g_xlnH);
    cudaGetSymbolAddress((void**)&xvTH, g_xvTH);

    const long SD  = (long)S_ * D_;
    const long FD  = (long)F_ * D_;
    const long HDD = (long)HD_ * D_;
    const long FHD = (long)F_ * HD_;

    cudaFuncSetAttribute(mma_k<2>, cudaFuncAttributeMaxDynamicSharedMemorySize, MMA_SMEM);
    cudaFuncSetAttribute(mma_k<1>, cudaFuncAttributeMaxDynamicSharedMemorySize, MMA_SMEM);
    cudaFuncSetAttribute(out_k, cudaFuncAttributeMaxDynamicSharedMemorySize, MMA_SMEM);
    cudaFuncSetAttribute(z_k, cudaFuncAttributeMaxDynamicSharedMemorySize, Z_SMEM);
    cudaFuncSetAttribute(spmm_mma_k, cudaFuncAttributeMaxDynamicSharedMemorySize, SPMM_SMEM);

    detect_mask_k<<<1, 256>>>(mask);
    count_k<<<(F_ * 32 + 255) / 256, 256>>>(mask);
    scan_k<<<1, 256>>>();
    fill_k<<<(F_ * 32 + 255) / 256, 256>>>(mask);

    casts_k<<<(int)(((long)B_ * H_ * S_ * S_ + 255) / 256), 256>>>(
        W_enc, W_O, probs, act, lns);
    tpose_wv_k<<<dim3(D_ / 32, DH_ / 32, H_), dim3(32, 8)>>>(W_V);
    tpose_wdec_k<<<dim3(F_ / 32, D_ / 32), dim3(32, 8)>>>(W_dec);
    prep_upT_k<<<dim3(F_ / 32, BS_ / 32), dim3(32, 8)>>>(pf, lns);

    // bias vectors (rank-64)
    t_k<<<H_, DH_>>>(W_V, upb);
    c2_k<<<3, 256>>>(W_O);
    bias_vec_k<<<F_ / 256, 256>>>(W_enc, b_enc, b_dec);

    // E1 and wd2 in one batched GEMM (z=0: E1, z=1: wd2; fp32 + half outputs)
    mma_k<2><<<dim3(HD_ / 128, F_ / 128, 2), 256, MMA_SMEM>>>(
        Wa, Wb, EW, EWh, D_, D_, D_, HD_, 2,
        0, FD, 0, HDD, 0, FHD);

    // xvT[b][hdh][k] = WvT[hdh,:] . xlnH[b][k,:]   (half out)
    mma_k<1><<<dim3(S_ / 128, HD_ / 128, B_), 256, MMA_SMEM>>>(
        Wb + HDD, xlnH, out /*dummy*/, xvTH, D_, D_, D_, S_, 1,
        0, 0, SD, 0, (long)HD_ * S_, 0);

    // sparse vw (fp32 acc, wd2 in half, padded)
    vw_sparse_k<<<F_, 256>>>();

    // spMM on tensor cores: gather-GEMM, PURE WRITE of sparse Yt (occ 3)
    spmm_mma_k<<<dim3(F_, BS_ / NBK), 256, SPMM_SMEM>>>();

    // Z[b][q][hdh] = probs[b,h] . xvT (causal)
    z_k<<<dim3(1, S_ / 128, B_ * H_), 256, Z_SMEM>>>();

    // FUSED: out = Z.E1^T + probs.Yt_sparse(causal) + bias  (sole writer)
    out_k<<<dim3(F_ / 128, S_ / 128, B_), 256, MMA_SMEM>>>(out, lns);
}

// round 17
// speedup vs baseline: 1.0552x; 1.0074x over previous
#include <cuda_runtime.h>
#include <cuda_fp16.h>

// Problem constants
#define B_  4
#define S_  512
#define D_  768
#define H_  12
#define DH_ 64
#define F_  2048
#define BS_ (B_ * S_)          // 2048
#define HK_ (H_ * S_)          // 6144
#define HD_ (H_ * DH_)         // 768  (flattened head dim)
#define NNZCAP 262144          // cap on padded mask nonzeros (expected ~226K)

// ---------------- scratch (device globals; no allocations allowed) ----------
__device__ __half g_Wa  [2 * F_ * D_];        // [0]=W_enc half, [1]=W_decT half
__device__ __half g_Wb  [2 * HD_ * D_];       // [0]=W_O flat,  [1]=W_V^T flat
__device__ float  g_EW  [2 * F_ * HD_];       // [0]=E1 [f][hdh], [1]=wd2 fp32
__device__ __half g_EWh [2 * F_ * HD_];       // [0]=E1 half, [1]=wd2 half
__device__ __half g_xlnH [B_ * S_ * D_];      // half x_ln
__device__ __half g_xvTH [B_ * HD_ * S_];     // [b][hdh][k] half (transposed xv)
__device__ __half g_zH   [B_ * S_ * HD_];     // [b][q][hdh] half (probs . xv)
__device__ __half g_probsH[B_ * H_ * S_ * S_];// half probs (upper tri stays 0-init)
__device__ __half g_uplnTh[F_ * BS_];         // [g][bk] half (gather source)
__device__ __half g_YtH  [B_ * F_ * HK_];     // [b][f][h*S+k] half (SPARSE ONLY)
__device__ __half g_vwvalH[16 * NNZCAP];      // [h(pad16)][j] half compact masked vw
__device__ int    g_gidx [NNZCAP];
__device__ int    g_cnt  [F_];                // REAL (unpadded) per-row counts
__device__ int    g_rowptr[F_ + 1];           // padded-to-16 CSR row ptr
__device__ float  g_t    [HD_];               // W_V^T . upb
__device__ float  g_c    [D_];
__device__ float  g_bias0[F_];
__device__ float  g_e    [F_];
__device__ int    g_maskmode;

// ---------------- mask dtype detector (parallel) -----------------------------
__global__ void detect_mask_k(const unsigned char* __restrict__ m) {
    __shared__ int sF, sB;
    int tid = threadIdx.x;
    if (tid == 0) { sF = 0; sB = 0; }
    __syncthreads();
    int f = 0, b = 0;
    for (int i = tid; i < 65536; i += 256) {
        unsigned char v = m[i];
        if (v == 63 || v == 128) f = 1;
        else if (v != 0 && (i & 3) != 0) b = 1;
    }
    if (f) atomicOr(&sF, 1);
    if (b) atomicOr(&sB, 1);
    __syncthreads();
    if (tid == 0) g_maskmode = sF ? 2 : (sB ? 0 : 1);
}

__device__ __forceinline__ int mask_nz(const unsigned char* m, long idx, int mode) {
    if (mode == 0) return m[idx] != 0;
    if (mode == 1) return ((const int*)m)[idx] != 0;
    return ((const float*)m)[idx] != 0.f;
}

// ---------------- mask CSR builders (rows padded to multiples of 16) ---------
__global__ void count_k(const unsigned char* __restrict__ m) {
    int w = (blockIdx.x * blockDim.x + threadIdx.x) >> 5;
    int lane = threadIdx.x & 31;
    if (w >= F_) return;
    int mode = g_maskmode;
    int cnt = 0;
    for (int g0 = 0; g0 < F_; g0 += 32) {
        int v = mask_nz(m, (long)w * F_ + g0 + lane, mode);
        cnt += __popc(__ballot_sync(0xffffffffu, v));
    }
    if (lane == 0) g_cnt[w] = cnt;
}

__global__ void scan_k() {
    __shared__ int part[256];
    int t = threadIdx.x;
    int base = t * 8;
    int s = 0;
    for (int i = 0; i < 8; i++) s += (g_cnt[base + i] + 15) & ~15;   // padded
    part[t] = s;
    __syncthreads();
    if (t == 0) {
        int r = 0;
        for (int i = 0; i < 256; i++) { int v = part[i]; part[i] = r; r += v; }
        g_rowptr[F_] = r;
    }
    __syncthreads();
    int r = part[t];
    for (int i = 0; i < 8; i++) {
        g_rowptr[base + i] = r;
        r += (g_cnt[base + i] + 15) & ~15;
    }
}

__global__ void fill_k(const unsigned char* __restrict__ m) {
    int w = (blockIdx.x * blockDim.x + threadIdx.x) >> 5;
    int lane = threadIdx.x & 31;
    if (w >= F_) return;
    int mode = g_maskmode;
    int base = g_rowptr[w];
    unsigned lt = (1u << lane) - 1u;
    for (int g0 = 0; g0 < F_; g0 += 32) {
        int g = g0 + lane;
        int v = mask_nz(m, (long)w * F_ + g, mode);
        unsigned bal = __ballot_sync(0xffffffffu, v);
        int pos = base + __popc(bal & lt);
        if (v && pos < NNZCAP) g_gidx[pos] = g;
        base += __popc(bal);
    }
    // pad slots -> g = 0 (vw pads are 0, so contribution is 0)
    int pe = g_rowptr[w + 1];
    if (pe > NNZCAP) pe = NNZCAP;
    for (int p = base + lane; p < pe; p += 32) g_gidx[p] = 0;
}

// ---------------- merged casts: W_enc, W_O, x_ln, probs -> half --------------
// probs: skip strictly-upper-triangle (k > q) writes; those stay 0 from
// zero-init, matching softmax(-1e9) == 0 exactly.
__global__ void casts_k(const float* __restrict__ wenc, const float* __restrict__ wo,
                        const float* __restrict__ probs,
                        const float* __restrict__ act, const float* __restrict__ lns) {
    long i = (long)blockIdx.x * blockDim.x + threadIdx.x;
    if (i < (long)F_ * D_)          g_Wa[i]     = __float2half(wenc[i]);
    if (i < (long)HD_ * D_)         g_Wb[i]     = __float2half(wo[i]);
    if (i < (long)B_ * S_ * D_)     g_xlnH[i]   = __float2half(act[i] / lns[i / D_]);
    if (i < (long)B_ * H_ * S_ * S_) {
        int k = (int)(i & (S_ - 1));
        int q = (int)((i >> 9) & (S_ - 1));
        if (k <= q) g_probsH[i] = __float2half(probs[i]);
    }
}

// W_V [h][m][dh] -> Wb[1] = WvTh[h*64+dh][m] half
__global__ void tpose_wv_k(const float* __restrict__ wv) {
    __shared__ float tile[32][33];
    int tx = threadIdx.x, ty = threadIdx.y;
    int h = blockIdx.z;
    int m0 = blockIdx.x * 32, dh0 = blockIdx.y * 32;
    #pragma unroll
    for (int i = 0; i < 32; i += 8)
        tile[ty + i][tx] = wv[((long)h * D_ + m0 + ty + i) * DH_ + dh0 + tx];
    __syncthreads();
    #pragma unroll
    for (int i = 0; i < 32; i += 8)
        g_Wb[(long)HD_ * D_ + ((long)h * DH_ + dh0 + ty + i) * D_ + m0 + tx] =
            __float2half(tile[tx][ty + i]);
}

// W_dec [m][g] -> Wa[1] = WdecT[g][m] half
__global__ void tpose_wdec_k(const float* __restrict__ wd) {
    __shared__ float tile[32][33];
    int tx = threadIdx.x, ty = threadIdx.y;
    int g = blockIdx.x * 32 + tx;
    int m0 = blockIdx.y * 32;
    #pragma unroll
    for (int i = 0; i < 32; i += 8)
        tile[ty + i][tx] = wd[(long)(m0 + ty + i) * F_ + g];
    __syncthreads();
    int mOut = m0 + tx;
    #pragma unroll
    for (int i = 0; i < 32; i += 8)
        g_Wa[(long)F_ * D_ + (long)(blockIdx.x * 32 + ty + i) * D_ + mOut] =
            __float2half(tile[tx][ty + i]);
}

__global__ void prep_upT_k(const float* __restrict__ pf, const float* __restrict__ lns) {
    __shared__ float tile[32][33];
    int tx = threadIdx.x, ty = threadIdx.y;
    int g = blockIdx.x * 32 + tx;
    int bk0 = blockIdx.y * 32;
    #pragma unroll
    for (int i = 0; i < 32; i += 8) {
        int bk = bk0 + ty + i;
        tile[ty + i][tx] = pf[(long)bk * F_ + g] / lns[bk];
    }
    __syncthreads();
    int bkOut = bk0 + tx;
    #pragma unroll
    for (int i = 0; i < 32; i += 8)
        g_uplnTh[(long)(blockIdx.x * 32 + ty + i) * BS_ + bkOut] =
            __float2half(tile[tx][ty + i]);
}

// ---------------- bias vectors (rank-64 path) --------------------------------
__global__ void t_k(const float* __restrict__ wv, const float* __restrict__ upb) {
    int h = blockIdx.x, dh = threadIdx.x;   // grid H_, block 64
    float s = 0.f;
    for (int m = 0; m < D_; m++)
        s += wv[((long)h * D_ + m) * DH_ + dh] * upb[m];
    g_t[h * DH_ + dh] = s;
}
__global__ void c2_k(const float* __restrict__ wo) {
    int d = blockIdx.x * 256 + threadIdx.x;  // grid 3, block 256
    if (d >= D_) return;
    float s = 0.f;
    for (int i = 0; i < HD_; i++) s += wo[(long)i * D_ + d] * g_t[i];
    g_c[d] = s;
}

__global__ void bias_vec_k(const float* __restrict__ W_enc,
                           const float* __restrict__ b_enc,
                           const float* __restrict__ b_dec) {
    int f = blockIdx.x * 256 + threadIdx.x;
    if (f >= F_) return;
    const float* row = W_enc + (long)f * D_;
    float s0 = 0.f, s1 = 0.f;
    for (int d = 0; d < D_; d++) {
        float w = row[d];
        s0 += w * b_dec[d];
        s1 += w * g_c[d];
    }
    g_bias0[f] = b_enc[f] - s0;
    g_e[f] = s1;
}

// ====== fp16 mma.sync m16n8k16 GEMM, cp.async 3-stage + ldmatrix (NT) ========
// OUTM 0: fp32 store.  1: half store.  2: fp32 + half.
#define MK   64
#define ROWH 72                               // halfs per smem row (64 + 8 pad)
#define NSTG 3
#define STGB (128 * ROWH * 2)                 // bytes per operand stage (18432)
#define MMA_SMEM (NSTG * 2 * STGB)            // 110592 bytes

__device__ __forceinline__ unsigned smem_u32(const void* p) {
    unsigned a;
    asm("{ .reg .u64 t; cvta.to.shared.u64 t, %1; cvt.u32.u64 %0, t; }" : "=r"(a) : "l"(p));
    return a;
}
__device__ __forceinline__ void cpasync16(unsigned dst, const void* src) {
    asm volatile("cp.async.cg.shared.global [%0], [%1], 16;" :: "r"(dst), "l"(src) : "memory");
}
__device__ __forceinline__ void ldsm_x4(unsigned addr, unsigned& r0, unsigned& r1,
                                        unsigned& r2, unsigned& r3) {
    asm volatile("ldmatrix.sync.aligned.m8n8.x4.shared.b16 {%0,%1,%2,%3}, [%4];"
                 : "=r"(r0), "=r"(r1), "=r"(r2), "=r"(r3) : "r"(addr));
}
__device__ __forceinline__ void ldsm_x4t(unsigned addr, unsigned& r0, unsigned& r1,
                                         unsigned& r2, unsigned& r3) {
    asm volatile("ldmatrix.sync.aligned.m8n8.x4.trans.shared.b16 {%0,%1,%2,%3}, [%4];"
                 : "=r"(r0), "=r"(r1), "=r"(r2), "=r"(r3) : "r"(addr));
}
__device__ __forceinline__ void mma16816(float* c, unsigned a0, unsigned a1,
                                         unsigned a2, unsigned a3,
                                         unsigned b0, unsigned b1) {
    asm volatile(
        "mma.sync.aligned.m16n8k16.row.col.f32.f16.f16.f32 "
        "{%0,%1,%2,%3}, {%4,%5,%6,%7}, {%8,%9}, {%0,%1,%2,%3};"
        : "+f"(c[0]), "+f"(c[1]), "+f"(c[2]), "+f"(c[3])
        : "r"(a0), "r"(a1), "r"(a2), "r"(a3), "r"(b0), "r"(b1));
}

template<int OUTM>
__global__ __launch_bounds__(256, 2)
void mma_k(const __half* __restrict__ Ag, const __half* __restrict__ Bg,
           float* __restrict__ Cg, __half* __restrict__ Chg,
           int K, int lda, int ldb, int ldc, int Hdim,
           long sAb, long sAh, long sBb, long sBh, long sCb, long sCh) {
    extern __shared__ __align__(16) char smc[];

    const int zb = blockIdx.z / Hdim, zh = blockIdx.z % Hdim;
    const __half* A = Ag + zb * sAb + zh * sAh;
    const __half* B = Bg + zb * sBb + zh * sBh;
    float*  C  = Cg  + zb * sCb + zh * sCh;
    __half* Ch = Chg + zb * sCb + zh * sCh;

    const int row0 = blockIdx.y * 128, col0 = blockIdx.x * 128;
    const int tid = threadIdx.x, wid = tid >> 5, lane = tid & 31;
    const int warpM = (wid & 1) * 64, warpN = (wid >> 1) * 32;
    const int lr = lane >> 2, lc = lane & 3;

    float acc[4][4][4];
    #pragma unroll
    for (int im = 0; im < 4; im++)
        #pragma unroll
        for (int in = 0; in < 4; in++)
            #pragma unroll
            for (int q = 0; q < 4; q++) acc[im][in][q] = 0.f;

    const int nch = K / MK;

    const unsigned sb32 = smem_u32(smc);
    const int lrow8 = lane & 7, sel = lane >> 3;
    const unsigned aoff = (unsigned)(((warpM + (sel & 1) * 8 + lrow8) * ROWH
                                      + (sel >> 1) * 8)) * 2u;
    // paired-x4 B load: lanes 0-15 -> tile in (cols 0/8), 16-31 -> tile in+1
    const unsigned boff4 = (unsigned)(((warpN + (lane >> 4) * 8 + lrow8) * ROWH
                                       + ((lane >> 3) & 1) * 8)) * 2u;

    auto issue = [&](int c) {
        unsigned sa = sb32 + (unsigned)((c % NSTG) * 2 * STGB);
        const int k0 = c * MK;
        #pragma unroll
        for (int i = 0; i < 4; i++) {
            int u = i * 256 + tid;
            int r = u >> 3, q = u & 7;
            unsigned off = (unsigned)(r * ROWH + q * 8) * 2u;
            cpasync16(sa + off, A + (long)(row0 + r) * lda + k0 + q * 8);
            cpasync16(sa + (unsigned)STGB + off, B + (long)(col0 + r) * ldb + k0 + q * 8);
        }
    };

    issue(0);
    asm volatile("cp.async.commit_group;" ::: "memory");
    if (nch > 1) issue(1);
    asm volatile("cp.async.commit_group;" ::: "memory");

    for (int c = 0; c < nch; c++) {
        asm volatile("cp.async.wait_group 1;" ::: "memory");
        __syncthreads();
        if (c + 2 < nch) issue(c + 2);
        asm volatile("cp.async.commit_group;" ::: "memory");

        const unsigned sAa = sb32 + (unsigned)((c % NSTG) * 2 * STGB);
        const unsigned sBa = sAa + (unsigned)STGB;
        #pragma unroll
        for (int ks = 0; ks < 4; ks++) {
            unsigned af[4][4], bf[4][2];
            #pragma unroll
            for (int im = 0; im < 4; im++)
                ldsm_x4(sAa + aoff + (unsigned)((im * 16 * ROWH + ks * 16) * 2),
                        af[im][0], af[im][1], af[im][2], af[im][3]);
            #pragma unroll
            for (int in = 0; in < 4; in += 2)
                ldsm_x4(sBa + boff4 + (unsigned)((in * 8 * ROWH + ks * 16) * 2),
                        bf[in][0], bf[in][1], bf[in + 1][0], bf[in + 1][1]);
            #pragma unroll
            for (int im = 0; im < 4; im++)
                #pragma unroll
                for (int in = 0; in < 4; in++)
                    mma16816(acc[im][in], af[im][0], af[im][1], af[im][2], af[im][3],
                             bf[in][0], bf[in][1]);
        }
    }

    #pragma unroll
    for (int im = 0; im < 4; im++) {
        int r = row0 + warpM + im * 16 + lr;
        #pragma unroll
        for (int in = 0; in < 4; in++) {
            int cc = col0 + warpN + in * 8 + lc * 2;
            float v0 = acc[im][in][0], v1 = acc[im][in][1];
            float v2 = acc[im][in][2], v3 = acc[im][in][3];
            if (OUTM == 0 || OUTM == 2) {
                *reinterpret_cast<float2*>(C + (long)r * ldc + cc) = make_float2(v0, v1);
                *reinterpret_cast<float2*>(C + (long)(r + 8) * ldc + cc) = make_float2(v2, v3);
            }
            if (OUTM == 1 || OUTM == 2) {
                *reinterpret_cast<__half2*>(Ch + (long)r * ldc + cc) =
                    __floats2half2_rn(v0, v1);
                *reinterpret_cast<__half2*>(Ch + (long)(r + 8) * ldc + cc) =
                    __floats2half2_rn(v2, v3);
            }
        }
    }
}

// ======== z_k: Z[b][q][h*64+n] = probs[b,h] (512x512) . xvT[h*64+n][k] =======
#define ZROW 72
#define ZSTG ((128 + 64) * ZROW * 2)           // 27648 B per stage
#define Z_SMEM (3 * ZSTG)                      // 82944 B

__global__ __launch_bounds__(256, 2)
void z_k() {
    extern __shared__ __align__(16) char smz[];
    const int b = blockIdx.z / H_, h = blockIdx.z % H_;
    const __half* A = g_probsH + (long)(b * H_ + h) * (S_ * S_);  // [q][k]
    const __half* Bx = g_xvTH + (long)b * HD_ * S_ + (long)(h * DH_) * S_; // [n][k]
    const int row0 = blockIdx.y * 128;
    const int tid = threadIdx.x, wid = tid >> 5, lane = tid & 31;
    const int warpM = (wid & 3) * 32, warpN = (wid >> 2) * 32;
    const int lr = lane >> 2, lc = lane & 3;

    float acc[2][4][4];
    #pragma unroll
    for (int im = 0; im < 2; im++)
        #pragma unroll
        for (int in = 0; in < 4; in++)
            #pragma unroll
            for (int q = 0; q < 4; q++) acc[im][in][q] = 0.f;

    const int nch = min(8, 2 * (int)blockIdx.y + 2);
    const unsigned sb32 = smem_u32(smz);
    const int lrow8 = lane & 7, sel = lane >> 3;
    const unsigned aoff = (unsigned)(((warpM + (sel & 1) * 8 + lrow8) * ZROW
                                      + (sel >> 1) * 8)) * 2u;
    const unsigned boff4 = (unsigned)(((warpN + (lane >> 4) * 8 + lrow8) * ZROW
                                       + ((lane >> 3) & 1) * 8)) * 2u;

    auto issue = [&](int c) {
        unsigned sa = sb32 + (unsigned)((c % 3) * ZSTG);
        const int k0 = c * 64;
        #pragma unroll
        for (int i = 0; i < 4; i++) {
            int u = i * 256 + tid;
            int r = u >> 3, q = u & 7;
            cpasync16(sa + (unsigned)(r * ZROW + q * 8) * 2u,
                      A + (long)(row0 + r) * S_ + k0 + q * 8);
        }
        #pragma unroll
        for (int i = 0; i < 2; i++) {
            int u = i * 256 + tid;
            int r = u >> 3, q = u & 7;
            cpasync16(sa + (unsigned)(128 * ZROW) * 2u + (unsigned)(r * ZROW + q * 8) * 2u,
                      Bx + (long)r * S_ + k0 + q * 8);
        }
    };

    issue(0);
    asm volatile("cp.async.commit_group;" ::: "memory");
    if (nch > 1) issue(1);
    asm volatile("cp.async.commit_group;" ::: "memory");

    for (int c = 0; c < nch; c++) {
        asm volatile("cp.async.wait_group 1;" ::: "memory");
        __syncthreads();
        if (c + 2 < nch) issue(c + 2);
        asm volatile("cp.async.commit_group;" ::: "memory");

        const unsigned sAa = sb32 + (unsigned)((c % 3) * ZSTG);
        const unsigned sBa = sAa + (unsigned)(128 * ZROW) * 2u;
        #pragma unroll
        for (int ks = 0; ks < 4; ks++) {
            unsigned af[2][4], bf[4][2];
            #pragma unroll
            for (int im = 0; im < 2; im++)
                ldsm_x4(sAa + aoff + (unsigned)((im * 16 * ZROW + ks * 16) * 2),
                        af[im][0], af[im][1], af[im][2], af[im][3]);
            #pragma unroll
            for (int in = 0; in < 4; in += 2)
                ldsm_x4(sBa + boff4 + (unsigned)((in * 8 * ZROW + ks * 16) * 2),
                        bf[in][0], bf[in][1], bf[in + 1][0], bf[in + 1][1]);
            #pragma unroll
            for (int im = 0; im < 2; im++)
                #pragma unroll
                for (int in = 0; in < 4; in++)
                    mma16816(acc[im][in], af[im][0], af[im][1], af[im][2], af[im][3],
                             bf[in][0], bf[in][1]);
        }
    }

    __half* Z = g_zH + (long)b * S_ * HD_;
    #pragma unroll
    for (int im = 0; im < 2; im++) {
        int r = row0 + warpM + im * 16 + lr;
        #pragma unroll
        for (int in = 0; in < 4; in++) {
            int cc = h * DH_ + warpN + in * 8 + lc * 2;
            *reinterpret_cast<__half2*>(Z + (long)r * HD_ + cc) =
                __floats2half2_rn(acc[im][in][0], acc[im][in][1]);
            *reinterpret_cast<__half2*>(Z + (long)(r + 8) * HD_ + cc) =
                __floats2half2_rn(acc[im][in][2], acc[im][in][3]);
        }
    }
}

// ======== out_k: FUSED final GEMM ===========================================
// out[b][q][f] = Z[b][q,:HD] . E1h[f,:HD]^T                (chunks 0..11)
//             + sum_h probs[b,h][q,:] . Yt[b][f, hS:hS+S]  (causal chunks)
//             + bias0[f] + e[f]/lns[b,q]
#define DENSE_CH (HD_ / MK)                   // 12 dense chunks (K = 768)

__global__ __launch_bounds__(256, 2)
void out_k(float* __restrict__ out, const float* __restrict__ Lg) {
    extern __shared__ __align__(16) char smc[];
    const int zb = blockIdx.z;
    const __half* Z = g_zH + (long)zb * S_ * HD_;
    const __half* P = g_probsH + (long)zb * H_ * (S_ * S_);
    const __half* Y = g_YtH + (long)zb * F_ * HK_;
    float* C = out + (long)zb * S_ * F_;

    const int row0 = blockIdx.y * 128, col0 = blockIdx.x * 128;
    const int tid = threadIdx.x, wid = tid >> 5, lane = tid & 31;
    const int warpM = (wid & 1) * 64, warpN = (wid >> 1) * 32;
    const int lr = lane >> 2, lc = lane & 3;

    float acc[4][4][4];
    #pragma unroll
    for (int im = 0; im < 4; im++)
        #pragma unroll
        for (int in = 0; in < 4; in++)
            #pragma unroll
            for (int q = 0; q < 4; q++) acc[im][in][q] = 0.f;

    const int nchh = min(8, 2 * (int)blockIdx.y + 2);
    const int nch = DENSE_CH + H_ * nchh;    // 12 dense + causal sparse chunks

    const unsigned sb32 = smem_u32(smc);
    const int lrow8 = lane & 7, sel = lane >> 3;
    const unsigned aoff = (unsigned)(((warpM + (sel & 1) * 8 + lrow8) * ROWH
                                      + (sel >> 1) * 8)) * 2u;
    const unsigned boff4 = (unsigned)(((warpN + (lane >> 4) * 8 + lrow8) * ROWH
                                       + ((lane >> 3) & 1) * 8)) * 2u;

    auto issue = [&](int c) {
        unsigned sa = sb32 + (unsigned)((c % NSTG) * 2 * STGB);
        const __half *Ab, *Bb;
        int kA, kB, ldaL, ldbL;
        if (c < DENSE_CH) {
            kA = c * MK; kB = kA;
            Ab = Z; ldaL = HD_;
            Bb = g_EWh; ldbL = HD_;
        } else {
            int idx = c - DENSE_CH;
            int hh = idx / nchh, cc = idx - hh * nchh;
            kA = cc * MK;
            kB = hh * S_ + kA;
            Ab = P + (long)hh * (S_ * S_); ldaL = S_;
            Bb = Y; ldbL = HK_;
        }
        #pragma unroll
        for (int i = 0; i < 4; i++) {
            int u = i * 256 + tid;
            int r = u >> 3, q = u & 7;
            unsigned off = (unsigned)(r * ROWH + q * 8) * 2u;
            cpasync16(sa + off, Ab + (long)(row0 + r) * ldaL + kA + q * 8);
            cpasync16(sa + (unsigned)STGB + off, Bb + (long)(col0 + r) * ldbL + kB + q * 8);
        }
    };

    issue(0);
    asm volatile("cp.async.commit_group;" ::: "memory");
    issue(1);
    asm volatile("cp.async.commit_group;" ::: "memory");

    for (int c = 0; c < nch; c++) {
        asm volatile("cp.async.wait_group 1;" ::: "memory");
        __syncthreads();
        if (c + 2 < nch) issue(c + 2);
        asm volatile("cp.async.commit_group;" ::: "memory");

        const unsigned sAa = sb32 + (unsigned)((c % NSTG) * 2 * STGB);
        const unsigned sBa = sAa + (unsigned)STGB;
        #pragma unroll
        for (int ks = 0; ks < 4; ks++) {
            unsigned af[4][4], bf[4][2];
            #pragma unroll
            for (int im = 0; im < 4; im++)
                ldsm_x4(sAa + aoff + (unsigned)((im * 16 * ROWH + ks * 16) * 2),
                        af[im][0], af[im][1], af[im][2], af[im][3]);
            #pragma unroll
            for (int in = 0; in < 4; in += 2)
                ldsm_x4(sBa + boff4 + (unsigned)((in * 8 * ROWH + ks * 16) * 2),
                        bf[in][0], bf[in][1], bf[in + 1][0], bf[in + 1][1]);
            #pragma unroll
            for (int im = 0; im < 4; im++)
                #pragma unroll
                for (int in = 0; in < 4; in++)
                    mma16816(acc[im][in], af[im][0], af[im][1], af[im][2], af[im][3],
                             bf[in][0], bf[in][1]);
        }
    }

    #pragma unroll
    for (int im = 0; im < 4; im++) {
        int r = row0 + warpM + im * 16 + lr;
        float il0 = 1.f / Lg[zb * S_ + r];
        float il1 = 1.f / Lg[zb * S_ + r + 8];
        #pragma unroll
        for (int in = 0; in < 4; in++) {
            int cc = col0 + warpN + in * 8 + lc * 2;
            float b0 = g_bias0[cc], b1 = g_bias0[cc + 1];
            float e0 = g_e[cc],     e1 = g_e[cc + 1];
            *reinterpret_cast<float2*>(C + (long)r * F_ + cc) =
                make_float2(acc[im][in][0] + b0 + e0 * il0,
                            acc[im][in][1] + b1 + e1 * il0);
            *reinterpret_cast<float2*>(C + (long)(r + 8) * F_ + cc) =
                make_float2(acc[im][in][2] + b0 + e0 * il1,
                            acc[im][in][3] + b1 + e1 * il1);
        }
    }
}

// ---------- sparse vw: vwvalH[h][j] = sum_dh E1[f][h64+dh]*wd2h[g][h64+dh] ---
__global__ __launch_bounds__(256)
void vw_sparse_k() {
    __shared__ float sE[HD_];
    const int f = blockIdx.x;
    const int tid = threadIdx.x;

    for (int i = tid; i < HD_; i += 256) sE[i] = g_EW[(long)f * HD_ + i];
    __syncthreads();

    const int jb = g_rowptr[f];
    int jePad = g_rowptr[f + 1];
    if (jePad > NNZCAP) jePad = NNZCAP;
    const int jeReal = min(jb + g_cnt[f], jePad);

    const int jl = tid / H_, h = tid - jl * H_;   // 21 j-slots x 12 heads = 252
    if (tid < 252) {
        for (int j = jb + jl; j < jePad; j += 21) {
            float s = 0.f;
            if (j < jeReal) {
                const int g = g_gidx[j];
                const __half* w = g_EWh + (long)F_ * HD_ + (long)g * HD_ + h * DH_;
                const float* e = sE + h * DH_;
                #pragma unroll
                for (int d = 0; d < DH_; d += 8) {
                    uint4 wp = *reinterpret_cast<const uint4*>(w + d);
                    const __half2* wh = reinterpret_cast<const __half2*>(&wp);
                    #pragma unroll
                    for (int q = 0; q < 4; q++) {
                        float2 wv = __half22float2(wh[q]);
                        s += e[d + q * 2 + 0] * wv.x;
                        s += e[d + q * 2 + 1] * wv.y;
                    }
                }
            }
            g_vwvalH[(long)h * NNZCAP + j] = __float2half(s);
        }
    }
    {
        int jl2 = tid >> 2, hr = 12 + (tid & 3);
        for (int j = jb + jl2; j < jePad; j += 64)
            g_vwvalH[(long)hr * NNZCAP + j] = __half(0.f);
    }
}

// ======== spMM as gather-GEMM (tensor cores), PURE WRITE into YtH ============
// Per (f, half-of-bk): Yt[h][bk] += sum_j vwvalH[h][j] * uplnTh[gidx[j]][bk]
// M=16 (h pad), K=nnz_f (padded 16), N=1024 per block. grid (F_, 2), 8 warps,
// warp w owns 128 bk cols. Double-buffered cp.async row gather, occupancy 3.
#define NBK  1024                              // bk columns per block
#define UPADW2 (NBK + 8)                       // halfs per gathered row
#define SPMM_STG (16 * UPADW2 * 2)             // 33024 B per stage
#define SPMM_SMEM (2 * SPMM_STG)               // 66048 B

__global__ __launch_bounds__(256, 3)
void spmm_mma_k() {
    extern __shared__ __align__(16) char sms[];
    const int f = blockIdx.x;
    const int bkbase = blockIdx.y * NBK;
    const int jb = g_rowptr[f];
    int je = g_rowptr[f + 1];
    if (je > NNZCAP) je = jb + ((NNZCAP - jb) & ~15);
    const int nch = (je - jb) >> 4;

    const int tid = threadIdx.x, wid = tid >> 5, lane = tid & 31;
    const int bk0 = wid * 128;                 // within block's 1024
    const unsigned sb32 = smem_u32(sms);

    float acc[16][4];
    #pragma unroll
    for (int nt = 0; nt < 16; nt++)
        #pragma unroll
        for (int q = 0; q < 4; q++) acc[nt][q] = 0.f;

    auto gather = [&](int c) {
        unsigned sa = sb32 + (unsigned)((c & 1) * SPMM_STG);
        const int j0 = jb + c * 16;
        #pragma unroll
        for (int i = 0; i < 8; i++) {
            int u = i * 256 + tid;             // 0..2047
            int row = u >> 7, q = u & 127;     // row 0..15, 16B-quad 0..127
            int g = g_gidx[j0 + row];
            cpasync16(sa + (unsigned)(row * UPADW2 + q * 8) * 2u,
                      g_uplnTh + (long)g * BS_ + bkbase + q * 8);
        }
    };

    if (nch > 0) {
        gather(0);
        asm volatile("cp.async.commit_group;" ::: "memory");

        const int arow = lane >> 2, acol = (lane & 3) * 2;
        const unsigned ldoff = (unsigned)((lane & 15) * UPADW2 + (lane >> 4) * 8) * 2u;

        for (int c = 0; c < nch; c++) {
            if (c + 1 < nch) gather(c + 1);
            asm volatile("cp.async.commit_group;" ::: "memory");
            asm volatile("cp.async.wait_group 1;" ::: "memory");
            __syncthreads();

            const int j0 = jb + c * 16;
            unsigned a0 = *reinterpret_cast<const unsigned*>(
                g_vwvalH + (long)arow * NNZCAP + j0 + acol);
            unsigned a1 = *reinterpret_cast<const unsigned*>(
                g_vwvalH + (long)(arow + 8) * NNZCAP + j0 + acol);
            unsigned a2 = *reinterpret_cast<const unsigned*>(
                g_vwvalH + (long)arow * NNZCAP + j0 + 8 + acol);
            unsigned a3 = *reinterpret_cast<const unsigned*>(
                g_vwvalH + (long)(arow + 8) * NNZCAP + j0 + 8 + acol);

            const unsigned sa = sb32 + (unsigned)((c & 1) * SPMM_STG) + ldoff;
            #pragma unroll
            for (int nt = 0; nt < 16; nt += 2) {
                unsigned b0, b1, b2, b3;
                ldsm_x4t(sa + (unsigned)(bk0 + nt * 8) * 2u, b0, b1, b2, b3);
                mma16816(acc[nt],     a0, a1, a2, a3, b0, b1);
                mma16816(acc[nt + 1], a0, a1, a2, a3, b2, b3);
            }
            __syncthreads();
        }
    }

    // epilogue: PURE STORE into YtH (sparse-only tensor; zero rows covered)
    const int h0 = lane >> 2, h1 = h0 + 8;
    #pragma unroll
    for (int nt = 0; nt < 16; nt++) {
        int col = bkbase + bk0 + nt * 8 + (lane & 3) * 2;
        int b = col >> 9, k = col & (S_ - 1);
        long base = ((long)b * F_ + f) * HK_ + k;
        *reinterpret_cast<__half2*>(&g_YtH[base + h0 * S_]) =
            __floats2half2_rn(acc[nt][0], acc[nt][1]);
        if (h1 < H_)
            *reinterpret_cast<__half2*>(&g_YtH[base + h1 * S_]) =
                __floats2half2_rn(acc[nt][2], acc[nt][3]);
    }
}

// ---------------------------------------------------------------------------
extern "C" void kernel_launch(void* const* d_in, const int* in_sizes, int n_in,
                              void* d_out, int out_size) {
    (void)in_sizes; (void)n_in; (void)out_size;
    const float* act   = (const float*)d_in[0];
    const float* lns   = (const float*)d_in[1];
    const float* probs = (const float*)d_in[2];
    const float* pf    = (const float*)d_in[3];
    const float* W_O   = (const float*)d_in[4];
    const float* W_V   = (const float*)d_in[5];
    const float* W_enc = (const float*)d_in[6];
    const float* b_enc = (const float*)d_in[7];
    const float* b_dec = (const float*)d_in[8];
    const float* W_dec = (const float*)d_in[9];
    const float* upb   = (const float*)d_in[10];
    const unsigned char* mask = (const unsigned char*)d_in[11];
    float* out = (float*)d_out;

    float *EW;
    __half *Wa, *Wb, *EWh, *xlnH, *xvTH;
    cudaGetSymbolAddress((void**)&Wa,   g_Wa);
    cudaGetSymbolAddress((void**)&Wb,   g_Wb);
    cudaGetSymbolAddress((void**)&EW,   g_EW);
    cudaGetSymbolAddress((void**)&EWh,  g_EWh);
    cudaGetSymbolAddress((void**)&xlnH, g_xlnH);
    cudaGetSymbolAddress((void**)&xvTH, g_xvTH);

    const long SD  = (long)S_ * D_;
    const long FD  = (long)F_ * D_;
    const long HDD = (long)HD_ * D_;
    const long FHD = (long)F_ * HD_;

    cudaFuncSetAttribute(mma_k<2>, cudaFuncAttributeMaxDynamicSharedMemorySize, MMA_SMEM);
    cudaFuncSetAttribute(mma_k<1>, cudaFuncAttributeMaxDynamicSharedMemorySize, MMA_SMEM);
    cudaFuncSetAttribute(out_k, cudaFuncAttributeMaxDynamicSharedMemorySize, MMA_SMEM);
    cudaFuncSetAttribute(z_k, cudaFuncAttributeMaxDynamicSharedMemorySize, Z_SMEM);
    cudaFuncSetAttribute(spmm_mma_k, cudaFuncAttributeMaxDynamicSharedMemorySize, SPMM_SMEM);

    detect_mask_k<<<1, 256>>>(mask);
    count_k<<<(F_ * 32 + 255) / 256, 256>>>(mask);
    scan_k<<<1, 256>>>();
    fill_k<<<(F_ * 32 + 255) / 256, 256>>>(mask);

    casts_k<<<(int)(((long)B_ * H_ * S_ * S_ + 255) / 256), 256>>>(
        W_enc, W_O, probs, act, lns);
    tpose_wv_k<<<dim3(D_ / 32, DH_ / 32, H_), dim3(32, 8)>>>(W_V);
    tpose_wdec_k<<<dim3(F_ / 32, D_ / 32), dim3(32, 8)>>>(W_dec);
    prep_upT_k<<<dim3(F_ / 32, BS_ / 32), dim3(32, 8)>>>(pf, lns);

    // bias vectors (rank-64)
    t_k<<<H_, DH_>>>(W_V, upb);
    c2_k<<<3, 256>>>(W_O);
    bias_vec_k<<<F_ / 256, 256>>>(W_enc, b_enc, b_dec);

    // E1 and wd2 in one batched GEMM (z=0: E1, z=1: wd2; fp32 + half outputs)
    mma_k<2><<<dim3(HD_ / 128, F_ / 128, 2), 256, MMA_SMEM>>>(
        Wa, Wb, EW, EWh, D_, D_, D_, HD_, 2,
        0, FD, 0, HDD, 0, FHD);

    // xvT[b][hdh][k] = WvT[hdh,:] . xlnH[b][k,:]   (half out)
    mma_k<1><<<dim3(S_ / 128, HD_ / 128, B_), 256, MMA_SMEM>>>(
        Wb + HDD, xlnH, out /*dummy*/, xvTH, D_, D_, D_, S_, 1,
        0, 0, SD, 0, (long)HD_ * S_, 0);

    // sparse vw (fp32 acc, wd2 in half, padded)
    vw_sparse_k<<<F_, 256>>>();

    // spMM on tensor cores: gather-GEMM, PURE WRITE of sparse Yt (occ 3)
    spmm_mma_k<<<dim3(F_, BS_ / NBK), 256, SPMM_SMEM>>>();

    // Z[b][q][hdh] = probs[b,h] . xvT (causal)
    z_k<<<dim3(1, S_ / 128, B_ * H_), 256, Z_SMEM>>>();

    // FUSED: out = Z.E1^T + probs.Yt_sparse(causal) + bias  (sole writer)
    out_k<<<dim3(F_ / 128, S_ / 128, B_), 256, MMA_SMEM>>>(out, lns);
}